// round 3
// baseline (speedup 1.0000x reference)
#include <cuda_runtime.h>
#include <math.h>

#define H   128
#define ED  64
#define MAXN 100000
#define MAXE 500000

typedef unsigned long long ull;

// ---------------- scratch (device globals; no allocations allowed) ----------------
__device__ float    g_h[(size_t)MAXN * H];      // LN1 output
__device__ float    g_msg[(size_t)MAXE * H];    // gated messages
__device__ float    g_score[MAXE];              // attention scores
__device__ float    g_exp[MAXE];                // exp(score - max)
__device__ unsigned g_maxkey[MAXN];             // ordered-uint segment max
__device__ float    g_denom[MAXN];              // segment sum of exp
__device__ float    g_agg[(size_t)MAXN * H];    // aggregated messages

// ---------------- packed f32x2 helpers ----------------
__device__ __forceinline__ ull pack2(float lo, float hi) {
    ull r; asm("mov.b64 %0, {%1, %2};" : "=l"(r) : "f"(lo), "f"(hi)); return r;
}
__device__ __forceinline__ float2 unpack2(ull v) {
    float lo, hi; asm("mov.b64 {%0, %1}, %2;" : "=f"(lo), "=f"(hi) : "l"(v));
    return make_float2(lo, hi);
}
__device__ __forceinline__ void ffma2(ull& d, ull a, ull b) {
    asm("fma.rn.f32x2 %0, %1, %2, %0;" : "+l"(d) : "l"(a), "l"(b));
}
__device__ __forceinline__ ull fadd2(ull a, ull b) {
    ull r; asm("add.rn.f32x2 %0, %1, %2;" : "=l"(r) : "l"(a), "l"(b)); return r;
}

__device__ __forceinline__ float gelu_exact(float v) {
    return 0.5f * v * (1.0f + erff(v * 0.70710678118654752440f));
}

// ---------------- packed tiled GEMM ----------------
// C[64 rows][128 cols] += A[64][K] * W[K][128]; A in smem (row stride lda),
// W streamed from global through a 32x128 smem tile. 256 threads,
// thread (ti,tj): rows ti*4..+3, cols tj*8..+7 held as 4 packed f32x2.
__device__ __forceinline__ void gemm_acc2(
    const float* __restrict__ As, int lda, int aoff,
    const float* __restrict__ Wg, int ldW, int woff,
    int K, float* __restrict__ Wts, ull acc[4][4])
{
    int tx = threadIdx.x;
    int ti = tx >> 4, tj = tx & 15;
    int c0 = tj * 8;
    const float* ap[4];
#pragma unroll
    for (int er = 0; er < 4; ++er) ap[er] = As + (ti * 4 + er) * lda + aoff;

    for (int kt = 0; kt < K; kt += 32) {
        __syncthreads();
#pragma unroll
        for (int i = 0; i < 4; ++i) {
            int f4 = tx + i * 256;          // 1024 float4 = 32x128 tile
            int r  = f4 >> 5;
            int c  = (f4 & 31) << 2;
            *(float4*)(Wts + r * 128 + c) =
                *(const float4*)(Wg + (size_t)(kt + r) * ldW + woff + c);
        }
        __syncthreads();
#pragma unroll 8
        for (int kk = 0; kk < 32; ++kk) {
            ull a2[4];
#pragma unroll
            for (int er = 0; er < 4; ++er) {
                float av = ap[er][kt + kk];
                a2[er] = pack2(av, av);
            }
            const ull* bp = (const ull*)(Wts + kk * 128 + c0);
            ull b2[4] = {bp[0], bp[1], bp[2], bp[3]};
#pragma unroll
            for (int er = 0; er < 4; ++er)
#pragma unroll
                for (int cj = 0; cj < 4; ++cj)
                    ffma2(acc[er][cj], a2[er], b2[cj]);
        }
    }
    __syncthreads();
}

__device__ __forceinline__ void init_acc2_bias(ull acc[4][4], const float* __restrict__ b) {
    const ull* bb = (const ull*)b;           // 32B-aligned (c0 multiple of 8 floats)
    ull bv[4] = {bb[0], bb[1], bb[2], bb[3]};
#pragma unroll
    for (int er = 0; er < 4; ++er)
#pragma unroll
        for (int cj = 0; cj < 4; ++cj) acc[er][cj] = bv[cj];
}

__device__ __forceinline__ void store_gelu(ull acc[4][4], float* __restrict__ Hm,
                                           int stride, int e0, int c0) {
#pragma unroll
    for (int er = 0; er < 4; ++er) {
        float* row = Hm + (e0 + er) * stride + c0;
        float2 p0 = unpack2(acc[er][0]), p1 = unpack2(acc[er][1]);
        float2 p2 = unpack2(acc[er][2]), p3 = unpack2(acc[er][3]);
        float4 v0 = make_float4(gelu_exact(p0.x), gelu_exact(p0.y),
                                gelu_exact(p1.x), gelu_exact(p1.y));
        float4 v1 = make_float4(gelu_exact(p2.x), gelu_exact(p2.y),
                                gelu_exact(p3.x), gelu_exact(p3.y));
        *(float4*)row = v0;
        *(float4*)(row + 4) = v1;
    }
}

// ---------------- K1: LayerNorm1 ----------------
__global__ __launch_bounds__(256) void ln1_kernel(
    const float* __restrict__ x, const float* __restrict__ g,
    const float* __restrict__ b, float* __restrict__ hout, int N)
{
    int node = blockIdx.x * 8 + (threadIdx.x >> 5);
    if (node >= N) return;
    int lane = threadIdx.x & 31;
    float4 v = ((const float4*)(x + (size_t)node * H))[lane];
    float s = v.x + v.y + v.z + v.w;
#pragma unroll
    for (int o = 16; o; o >>= 1) s += __shfl_xor_sync(0xffffffffu, s, o);
    float m = s * (1.0f / 128.0f);
    float dx = v.x - m, dy = v.y - m, dz = v.z - m, dw = v.w - m;
    float ss = dx * dx + dy * dy + dz * dz + dw * dw;
#pragma unroll
    for (int o = 16; o; o >>= 1) ss += __shfl_xor_sync(0xffffffffu, ss, o);
    float r = rsqrtf(ss * (1.0f / 128.0f) + 1e-5f);
    float4 gv = ((const float4*)g)[lane], bv = ((const float4*)b)[lane];
    float4 o4 = make_float4(dx * r * gv.x + bv.x, dy * r * gv.y + bv.y,
                            dz * r * gv.z + bv.z, dw * r * gv.w + bv.w);
    ((float4*)(hout + (size_t)node * H))[lane] = o4;
}

// ---------------- init: zero agg / denom / maxkey ----------------
__global__ __launch_bounds__(256) void init_kernel(int N)
{
    int i = blockIdx.x * 256 + threadIdx.x;
    if (i < N * H) g_agg[i] = 0.0f;
    if (i < N) { g_maxkey[i] = 0u; g_denom[i] = 0.0f; }
}

// ---------------- K2: per-edge MLPs (the big one) ----------------
__global__ __launch_bounds__(256, 1) void edge_kernel(
    const int* __restrict__ esrc, const int* __restrict__ edst,
    const float* __restrict__ emb,
    const float* __restrict__ Wm1, const float* __restrict__ bm1,
    const float* __restrict__ Wm2, const float* __restrict__ bm2,
    const float* __restrict__ Wa1, const float* __restrict__ ba1,
    const float* __restrict__ Wa2, const float* __restrict__ ba2,
    const float* __restrict__ Wg1, const float* __restrict__ bg1,
    const float* __restrict__ Wg2, const float* __restrict__ bg2,
    int E)
{
    extern __shared__ float sm[];
    float* Fe    = sm;                 // [64][324] features [h_dst | h_src | emb]
    float* Hm    = Fe + 64 * 324;      // [64][132] hidden buffer
    float* Wt    = Hm + 64 * 132;      // [32][128] weight tile
    float* gateS = Wt + 32 * 128;      // [64]

    int tx = threadIdx.x;
    int e_base = blockIdx.x * 64;

    { // gather features: 4 threads per edge
        int le = tx >> 2, q = tx & 3;
        int e = e_base + le;
        bool valid = e < E;
        int src = valid ? esrc[e] : 0;
        int dst = valid ? edst[e] : 0;
        const float4* hd = (const float4*)(g_h + (size_t)dst * H);
        const float4* hs = (const float4*)(g_h + (size_t)src * H);
        const float4* em4 = (const float4*)(emb + (size_t)e * ED);
        float4 z = make_float4(0.f, 0.f, 0.f, 0.f);
        float* fr = Fe + le * 324;
#pragma unroll
        for (int jj = 0; jj < 8; ++jj) { int j = q + jj * 4; *(float4*)(fr + j * 4) = valid ? hd[j] : z; }
#pragma unroll
        for (int jj = 0; jj < 8; ++jj) { int j = q + jj * 4; *(float4*)(fr + 128 + j * 4) = valid ? hs[j] : z; }
#pragma unroll
        for (int jj = 0; jj < 4; ++jj) { int j = q + jj * 4; *(float4*)(fr + 256 + j * 4) = valid ? em4[j] : z; }
    }
    __syncthreads();

    int ti = tx >> 4, tj = tx & 15;
    int e0 = ti * 4, c0 = tj * 8;
    ull acc[4][4];

    // ---- gate path: gelu(ctx @ Wg1 + bg1) @ Wg2 -> sigmoid
    init_acc2_bias(acc, bg1 + c0);
    gemm_acc2(Fe, 324, 0, Wg1, 128, 0, 320, Wt, acc);
    store_gelu(acc, Hm, 132, e0, c0);
    __syncthreads();
    { // 4 threads per row: 32 MACs each + quad shfl reduce
        int row = tx >> 2, q = tx & 3;
        const float* hr = Hm + row * 132 + q * 32;
        const float* w  = Wg2 + q * 32;
        float s = 0.f;
#pragma unroll 8
        for (int c = 0; c < 32; ++c) s = fmaf(hr[c], w[c], s);
        s += __shfl_xor_sync(0xffffffffu, s, 1);
        s += __shfl_xor_sync(0xffffffffu, s, 2);
        if (q == 0) gateS[row] = 1.0f / (1.0f + expf(-(s + bg2[0])));
    }
    __syncthreads();

    // ---- attn path
    init_acc2_bias(acc, ba1 + c0);
    gemm_acc2(Fe, 324, 0, Wa1, 128, 0, 320, Wt, acc);
    store_gelu(acc, Hm, 132, e0, c0);
    __syncthreads();
    {
        int row = tx >> 2, q = tx & 3;
        const float* hr = Hm + row * 132 + q * 32;
        const float* w  = Wa2 + q * 32;
        float s = 0.f;
#pragma unroll 8
        for (int c = 0; c < 32; ++c) s = fmaf(hr[c], w[c], s);
        s += __shfl_xor_sync(0xffffffffu, s, 1);
        s += __shfl_xor_sync(0xffffffffu, s, 2);
        int e = e_base + row;
        if (q == 0 && e < E) g_score[e] = s + ba2[0];
    }
    __syncthreads();

    // ---- msg path: gelu([h_src,emb] @ Wm1 + bm1) @ Wm2 + bm2, then * gate
    init_acc2_bias(acc, bm1 + c0);
    gemm_acc2(Fe, 324, 128, Wm1, 128, 0, 192, Wt, acc);
    store_gelu(acc, Hm, 132, e0, c0);
    init_acc2_bias(acc, bm2 + c0);
    gemm_acc2(Hm, 132, 0, Wm2, 128, 0, 128, Wt, acc);
#pragma unroll
    for (int er = 0; er < 4; ++er) {
        int e = e_base + e0 + er;
        if (e < E) {
            float g = gateS[e0 + er];
            float2 p0 = unpack2(acc[er][0]), p1 = unpack2(acc[er][1]);
            float2 p2 = unpack2(acc[er][2]), p3 = unpack2(acc[er][3]);
            float4 v0 = make_float4(p0.x * g, p0.y * g, p1.x * g, p1.y * g);
            float4 v1 = make_float4(p2.x * g, p2.y * g, p3.x * g, p3.y * g);
            float* mr = g_msg + (size_t)e * H + c0;
            *(float4*)mr = v0;
            *(float4*)(mr + 4) = v1;
        }
    }
}

// ---------------- K3: segment softmax ----------------
__global__ __launch_bounds__(256) void smax_kernel(const int* __restrict__ edst, int E)
{
    int e = blockIdx.x * 256 + threadIdx.x;
    if (e >= E) return;
    int i = __float_as_int(g_score[e]);
    unsigned key = (i >= 0) ? ((unsigned)i ^ 0x80000000u) : ~(unsigned)i;
    atomicMax(&g_maxkey[edst[e]], key);
}

__global__ __launch_bounds__(256) void exps_kernel(const int* __restrict__ edst, int E)
{
    int e = blockIdx.x * 256 + threadIdx.x;
    if (e >= E) return;
    int d = edst[e];
    unsigned k = g_maxkey[d];
    int bits = (k & 0x80000000u) ? (int)(k ^ 0x80000000u) : (int)~k;
    float m = __int_as_float(bits);
    float v = expf(g_score[e] - m);
    g_exp[e] = v;
    atomicAdd(&g_denom[d], v);
}

// ---------------- K4: edge_repr + scatter-add agg ----------------
__global__ __launch_bounds__(256) void scatter_kernel(
    const int* __restrict__ edst, float* __restrict__ erep, int E)
{
    int idx = blockIdx.x * 256 + threadIdx.x;
    int e = idx >> 5;
    if (e >= E) return;
    int l4 = idx & 31;
    int d = edst[e];
    float w = g_exp[e] / fmaxf(g_denom[d], 1e-12f);
    float4 m = ((const float4*)(g_msg + (size_t)e * H))[l4];
    float4 r = make_float4(m.x * w, m.y * w, m.z * w, m.w * w);
    ((float4*)(erep + (size_t)e * H))[l4] = r;
    float* ag = g_agg + (size_t)d * H + (size_t)l4 * 4;
    atomicAdd(ag + 0, r.x);
    atomicAdd(ag + 1, r.y);
    atomicAdd(ag + 2, r.z);
    atomicAdd(ag + 3, r.w);
}

// ---------------- K5: node update + LN2 + FFN ----------------
__global__ __launch_bounds__(256, 1) void node_kernel(
    const float* __restrict__ x,
    const float* __restrict__ Wself, const float* __restrict__ bself,
    const float* __restrict__ Wagg, const float* __restrict__ bagg,
    const float* __restrict__ g2, const float* __restrict__ b2,
    const float* __restrict__ Wf1, const float* __restrict__ bf1,
    const float* __restrict__ Wf2, const float* __restrict__ bf2,
    float* __restrict__ out, int N)
{
    extern __shared__ float sm[];
    float* At   = sm;                  // [64][132] A operand
    float* Ot   = At + 64 * 132;       // [64][132] out1 (pre-LN residual)
    float* H2   = Ot + 64 * 132;       // [64][260] FFN hidden
    float* Wt   = H2 + 64 * 260;       // [32][128]
    float* mu   = Wt + 32 * 128;       // [64]
    float* rstd = mu + 64;             // [64]

    int tx = threadIdx.x;
    int n_base = blockIdx.x * 64;
    int ti = tx >> 4, tj = tx & 15;
    int e0 = ti * 4, c0 = tj * 8;
    ull acc[4][4];

    { // gather h
        int le = tx >> 2, q = tx & 3;
        int n = n_base + le;
        bool valid = n < N;
        const float4* hr = (const float4*)(g_h + (size_t)(valid ? n : 0) * H);
        float* ar = At + le * 132;
        float4 z = make_float4(0.f, 0.f, 0.f, 0.f);
#pragma unroll
        for (int jj = 0; jj < 8; ++jj) { int j = q + jj * 4; *(float4*)(ar + j * 4) = valid ? hr[j] : z; }
    }

    { // acc = bself + bagg  (packed adds)
        const ull* bs = (const ull*)(bself + c0);
        const ull* bg = (const ull*)(bagg + c0);
        ull bv[4];
#pragma unroll
        for (int cj = 0; cj < 4; ++cj) bv[cj] = fadd2(bs[cj], bg[cj]);
#pragma unroll
        for (int er = 0; er < 4; ++er)
#pragma unroll
            for (int cj = 0; cj < 4; ++cj) acc[er][cj] = bv[cj];
    }
    gemm_acc2(At, 132, 0, Wself, 128, 0, 128, Wt, acc);

    { // overwrite At with agg (gemm_acc2's trailing sync makes this safe)
        int le = tx >> 2, q = tx & 3;
        int n = n_base + le;
        bool valid = n < N;
        const float4* gr = (const float4*)(g_agg + (size_t)(valid ? n : 0) * H);
        float* ar = At + le * 132;
        float4 z = make_float4(0.f, 0.f, 0.f, 0.f);
#pragma unroll
        for (int jj = 0; jj < 8; ++jj) { int j = q + jj * 4; *(float4*)(ar + j * 4) = valid ? gr[j] : z; }
    }
    gemm_acc2(At, 132, 0, Wagg, 128, 0, 128, Wt, acc);

    // out1 = x + update -> Ot
#pragma unroll
    for (int er = 0; er < 4; ++er) {
        int n = n_base + e0 + er;
        float4 x0 = make_float4(0.f, 0.f, 0.f, 0.f), x1 = x0;
        if (n < N) {
            x0 = *(const float4*)(x + (size_t)n * H + c0);
            x1 = *(const float4*)(x + (size_t)n * H + c0 + 4);
        }
        float2 p0 = unpack2(acc[er][0]), p1 = unpack2(acc[er][1]);
        float2 p2 = unpack2(acc[er][2]), p3 = unpack2(acc[er][3]);
        float4 o0 = make_float4(p0.x + x0.x, p0.y + x0.y, p1.x + x0.z, p1.y + x0.w);
        float4 o1 = make_float4(p2.x + x1.x, p2.y + x1.y, p3.x + x1.z, p3.y + x1.w);
        float* orow = Ot + (e0 + er) * 132 + c0;
        *(float4*)orow = o0;
        *(float4*)(orow + 4) = o1;
    }
    __syncthreads();

    // LN2 stats: 4 threads per row, single pass
    {
        int row = tx >> 2, q = tx & 3;
        const float* orow = Ot + row * 132 + q * 32;
        float s = 0.f, s2 = 0.f;
#pragma unroll 8
        for (int c = 0; c < 32; ++c) { float v = orow[c]; s += v; s2 = fmaf(v, v, s2); }
        s  += __shfl_xor_sync(0xffffffffu, s, 1);
        s  += __shfl_xor_sync(0xffffffffu, s, 2);
        s2 += __shfl_xor_sync(0xffffffffu, s2, 1);
        s2 += __shfl_xor_sync(0xffffffffu, s2, 2);
        if (q == 0) {
            float m = s * (1.0f / 128.0f);
            mu[row] = m;
            rstd[row] = rsqrtf(fmaxf(s2 * (1.0f / 128.0f) - m * m, 0.0f) + 1e-5f);
        }
    }
    __syncthreads();

    { // normalize -> At
        int le = tx & 63, cb = tx >> 6;
        float m = mu[le], r = rstd[le];
        const float* orow = Ot + le * 132;
        float* ar = At + le * 132;
#pragma unroll 4
        for (int c = cb * 32; c < cb * 32 + 32; ++c)
            ar[c] = (orow[c] - m) * r * g2[c] + b2[c];
    }

    // FFN layer 1: [64][128] @ [128][256] in two 128-col chunks
    for (int chunk = 0; chunk < 2; ++chunk) {
        int coff = chunk * 128;
        init_acc2_bias(acc, bf1 + coff + c0);
        gemm_acc2(At, 132, 0, Wf1, 256, coff, 128, Wt, acc);
        store_gelu(acc, H2 + coff, 260, e0, c0);
    }

    // FFN layer 2: [64][256] @ [256][128], + residual -> out
    init_acc2_bias(acc, bf2 + c0);
    gemm_acc2(H2, 260, 0, Wf2, 128, 0, 256, Wt, acc);
#pragma unroll
    for (int er = 0; er < 4; ++er) {
        int n = n_base + e0 + er;
        if (n < N) {
            const float* orow = Ot + (e0 + er) * 132 + c0;
            float2 p0 = unpack2(acc[er][0]), p1 = unpack2(acc[er][1]);
            float2 p2 = unpack2(acc[er][2]), p3 = unpack2(acc[er][3]);
            float4 o0 = make_float4(orow[0] + p0.x, orow[1] + p0.y,
                                    orow[2] + p1.x, orow[3] + p1.y);
            float4 o1 = make_float4(orow[4] + p2.x, orow[5] + p2.y,
                                    orow[6] + p3.x, orow[7] + p3.y);
            float* po = out + (size_t)n * H + c0;
            *(float4*)po = o0;
            *(float4*)(po + 4) = o1;
        }
    }
}

// ---------------- launch ----------------
extern "C" void kernel_launch(void* const* d_in, const int* in_sizes, int n_in,
                              void* d_out, int out_size)
{
    const float* x     = (const float*)d_in[0];
    const int*   esrc  = (const int*)d_in[1];
    const int*   edst  = (const int*)d_in[2];
    const float* emb   = (const float*)d_in[3];
    const float* ln1g  = (const float*)d_in[4];
    const float* ln1b  = (const float*)d_in[5];
    const float* ln2g  = (const float*)d_in[6];
    const float* ln2b  = (const float*)d_in[7];
    const float* Wself = (const float*)d_in[8];
    const float* bself = (const float*)d_in[9];
    const float* Wm1   = (const float*)d_in[10];
    const float* bm1   = (const float*)d_in[11];
    const float* Wm2   = (const float*)d_in[12];
    const float* bm2   = (const float*)d_in[13];
    const float* Wa1   = (const float*)d_in[14];
    const float* ba1   = (const float*)d_in[15];
    const float* Wa2   = (const float*)d_in[16];
    const float* ba2   = (const float*)d_in[17];
    const float* Wg1   = (const float*)d_in[18];
    const float* bg1   = (const float*)d_in[19];
    const float* Wg2   = (const float*)d_in[20];
    const float* bg2   = (const float*)d_in[21];
    const float* Wagg  = (const float*)d_in[22];
    const float* bagg  = (const float*)d_in[23];
    const float* Wf1   = (const float*)d_in[24];
    const float* bf1   = (const float*)d_in[25];
    const float* Wf2   = (const float*)d_in[26];
    const float* bf2   = (const float*)d_in[27];

    int N = in_sizes[0] / H;
    int E = in_sizes[1];

    float* out_nodes = (float*)d_out;
    float* out_edges = out_nodes + (size_t)N * H;

    const int EDGE_SMEM = (64 * 324 + 64 * 132 + 32 * 128 + 64) * 4;      // 133376
    const int NODE_SMEM = (64 * 132 * 2 + 64 * 260 + 32 * 128 + 128) * 4; // 151040
    cudaFuncSetAttribute(edge_kernel, cudaFuncAttributeMaxDynamicSharedMemorySize, EDGE_SMEM);
    cudaFuncSetAttribute(node_kernel, cudaFuncAttributeMaxDynamicSharedMemorySize, NODE_SMEM);

    float* hbuf;
    cudaGetSymbolAddress((void**)&hbuf, g_h);

    ln1_kernel<<<(N + 7) / 8, 256>>>(x, ln1g, ln1b, hbuf, N);
    init_kernel<<<(N * H + 255) / 256, 256>>>(N);
    edge_kernel<<<(E + 63) / 64, 256, EDGE_SMEM>>>(
        esrc, edst, emb, Wm1, bm1, Wm2, bm2, Wa1, ba1, Wa2, ba2,
        Wg1, bg1, Wg2, bg2, E);
    smax_kernel<<<(E + 255) / 256, 256>>>(edst, E);
    exps_kernel<<<(E + 255) / 256, 256>>>(edst, E);
    scatter_kernel<<<((size_t)E * 32 + 255) / 256, 256>>>(edst, out_edges, E);
    node_kernel<<<(N + 63) / 64, 256, NODE_SMEM>>>(
        x, Wself, bself, Wagg, bagg, ln2g, ln2b, Wf1, bf1, Wf2, bf2,
        out_nodes, N);
}

// round 8
// speedup vs baseline: 2.7263x; 2.7263x over previous
#include <cuda_runtime.h>
#include <math.h>

#define H   128
#define ED  64
#define MAXN 100000
#define MAXE 500000

// ---------------- scratch (device globals; no allocations allowed) ----------------
__device__ float    g_h[(size_t)MAXN * H];      // LN1 output
__device__ float    g_msg[(size_t)MAXE * H];    // gated messages
__device__ float    g_score[MAXE];              // attention scores
__device__ float    g_exp[MAXE];                // exp(score - max)
__device__ unsigned g_maxkey[MAXN];             // ordered-uint segment max
__device__ float    g_denom[MAXN];              // segment sum of exp
__device__ float    g_agg[(size_t)MAXN * H];    // aggregated messages
// node-level precomputed first-layer partials (no bias)
__device__ float    g_Pgd[(size_t)MAXN * H];    // h @ Wg1[0:128]    (dst part, gate)
__device__ float    g_Pgs[(size_t)MAXN * H];    // h @ Wg1[128:256]  (src part, gate)
__device__ float    g_Pad[(size_t)MAXN * H];    // h @ Wa1[0:128]    (dst part, attn)
__device__ float    g_Pas[(size_t)MAXN * H];    // h @ Wa1[128:256]  (src part, attn)
__device__ float    g_Pms[(size_t)MAXN * H];    // h @ Wm1[0:128]    (src part, msg)

// ---------------- helpers ----------------
__device__ __forceinline__ float gelu_exact(float v) {
    return 0.5f * v * (1.0f + erff(v * 0.70710678118654752440f));
}

// C[64 rows][128 cols] += A[64][K] * W[K][128]; A in smem (row stride lda),
// W streamed from global through a 32x128 smem tile. 256 threads,
// thread (ti,tj): rows ti*4..+3, cols tj*8..+7.
__device__ __forceinline__ void gemm_acc(
    const float* __restrict__ As, int lda, int aoff,
    const float* __restrict__ Wg, int ldW, int woff,
    int K, float* __restrict__ Wts, float acc[4][8])
{
    int tx = threadIdx.x;
    int ti = tx >> 4, tj = tx & 15;
    int c0 = tj * 8;
    const float* ap[4];
#pragma unroll
    for (int er = 0; er < 4; ++er) ap[er] = As + (ti * 4 + er) * lda + aoff;

    for (int kt = 0; kt < K; kt += 32) {
        __syncthreads();
#pragma unroll
        for (int i = 0; i < 4; ++i) {
            int f4 = tx + i * 256;          // 1024 float4 = 32x128 tile
            int r  = f4 >> 5;
            int c  = (f4 & 31) << 2;
            *(float4*)(Wts + r * 128 + c) =
                *(const float4*)(Wg + (size_t)(kt + r) * ldW + woff + c);
        }
        __syncthreads();
#pragma unroll 16
        for (int kk = 0; kk < 32; ++kk) {
            float av[4];
#pragma unroll
            for (int er = 0; er < 4; ++er) av[er] = ap[er][kt + kk];
            float4 b0 = *(const float4*)(Wts + kk * 128 + c0);
            float4 b1 = *(const float4*)(Wts + kk * 128 + c0 + 4);
            float bv[8] = {b0.x, b0.y, b0.z, b0.w, b1.x, b1.y, b1.z, b1.w};
#pragma unroll
            for (int er = 0; er < 4; ++er)
#pragma unroll
                for (int cj = 0; cj < 8; ++cj)
                    acc[er][cj] = fmaf(av[er], bv[cj], acc[er][cj]);
        }
    }
    __syncthreads();
}

__device__ __forceinline__ void init_acc_bias(float acc[4][8], const float* __restrict__ b) {
    float4 b0 = *(const float4*)b, b1 = *(const float4*)(b + 4);
    float bv[8] = {b0.x, b0.y, b0.z, b0.w, b1.x, b1.y, b1.z, b1.w};
#pragma unroll
    for (int er = 0; er < 4; ++er)
#pragma unroll
        for (int cj = 0; cj < 8; ++cj) acc[er][cj] = bv[cj];
}

// acc = Pd[dst] + Ps[src] + bias  (per-thread cells, direct from global/L2)
__device__ __forceinline__ void load_acc_pp(
    float acc[4][8], const float* __restrict__ Pd, const float* __restrict__ Ps,
    const int* dsts, const int* srcs, const float* __restrict__ b, int c0)
{
    float4 b0 = *(const float4*)(b + c0), b1 = *(const float4*)(b + c0 + 4);
    float bv[8] = {b0.x, b0.y, b0.z, b0.w, b1.x, b1.y, b1.z, b1.w};
#pragma unroll
    for (int er = 0; er < 4; ++er) {
        const float4* pd = (const float4*)(Pd + (size_t)dsts[er] * H + c0);
        const float4* ps = (const float4*)(Ps + (size_t)srcs[er] * H + c0);
        float4 d0 = pd[0], d1 = pd[1];
        float4 s0 = ps[0], s1 = ps[1];
        acc[er][0] = d0.x + s0.x + bv[0]; acc[er][1] = d0.y + s0.y + bv[1];
        acc[er][2] = d0.z + s0.z + bv[2]; acc[er][3] = d0.w + s0.w + bv[3];
        acc[er][4] = d1.x + s1.x + bv[4]; acc[er][5] = d1.y + s1.y + bv[5];
        acc[er][6] = d1.z + s1.z + bv[6]; acc[er][7] = d1.w + s1.w + bv[7];
    }
}

// acc = Ps[src] + bias
__device__ __forceinline__ void load_acc_p(
    float acc[4][8], const float* __restrict__ Ps,
    const int* srcs, const float* __restrict__ b, int c0)
{
    float4 b0 = *(const float4*)(b + c0), b1 = *(const float4*)(b + c0 + 4);
    float bv[8] = {b0.x, b0.y, b0.z, b0.w, b1.x, b1.y, b1.z, b1.w};
#pragma unroll
    for (int er = 0; er < 4; ++er) {
        const float4* ps = (const float4*)(Ps + (size_t)srcs[er] * H + c0);
        float4 s0 = ps[0], s1 = ps[1];
        acc[er][0] = s0.x + bv[0]; acc[er][1] = s0.y + bv[1];
        acc[er][2] = s0.z + bv[2]; acc[er][3] = s0.w + bv[3];
        acc[er][4] = s1.x + bv[4]; acc[er][5] = s1.y + bv[5];
        acc[er][6] = s1.z + bv[6]; acc[er][7] = s1.w + bv[7];
    }
}

__device__ __forceinline__ void store_hidden_gelu(float acc[4][8], float* __restrict__ Hm,
                                                  int stride, int e0, int c0) {
#pragma unroll
    for (int er = 0; er < 4; ++er) {
        float* row = Hm + (e0 + er) * stride + c0;
        float4 v0 = make_float4(gelu_exact(acc[er][0]), gelu_exact(acc[er][1]),
                                gelu_exact(acc[er][2]), gelu_exact(acc[er][3]));
        float4 v1 = make_float4(gelu_exact(acc[er][4]), gelu_exact(acc[er][5]),
                                gelu_exact(acc[er][6]), gelu_exact(acc[er][7]));
        *(float4*)row = v0;
        *(float4*)(row + 4) = v1;
    }
}

// ---------------- K1: LayerNorm1 ----------------
__global__ __launch_bounds__(256) void ln1_kernel(
    const float* __restrict__ x, const float* __restrict__ g,
    const float* __restrict__ b, float* __restrict__ hout, int N)
{
    int node = blockIdx.x * 8 + (threadIdx.x >> 5);
    if (node >= N) return;
    int lane = threadIdx.x & 31;
    float4 v = ((const float4*)(x + (size_t)node * H))[lane];
    float s = v.x + v.y + v.z + v.w;
#pragma unroll
    for (int o = 16; o; o >>= 1) s += __shfl_xor_sync(0xffffffffu, s, o);
    float m = s * (1.0f / 128.0f);
    float dx = v.x - m, dy = v.y - m, dz = v.z - m, dw = v.w - m;
    float ss = dx * dx + dy * dy + dz * dz + dw * dw;
#pragma unroll
    for (int o = 16; o; o >>= 1) ss += __shfl_xor_sync(0xffffffffu, ss, o);
    float r = rsqrtf(ss * (1.0f / 128.0f) + 1e-5f);
    float4 gv = ((const float4*)g)[lane], bv = ((const float4*)b)[lane];
    float4 o4 = make_float4(dx * r * gv.x + bv.x, dy * r * gv.y + bv.y,
                            dz * r * gv.z + bv.z, dw * r * gv.w + bv.w);
    ((float4*)(hout + (size_t)node * H))[lane] = o4;
}

// ---------------- K1b: node-level precompute of first-layer partials ----------------
__global__ __launch_bounds__(256, 2) void pre_kernel(
    const float* __restrict__ Wg1, const float* __restrict__ Wa1,
    const float* __restrict__ Wm1, int N)
{
    extern __shared__ float sm[];
    float* At = sm;                 // [64][132]
    float* Wt = At + 64 * 132;      // [32][128]

    int tx = threadIdx.x;
    int n_base = blockIdx.x * 64;
    { // gather h tile
        int le = tx >> 2, q = tx & 3;
        int n = n_base + le;
        bool valid = n < N;
        const float4* hr = (const float4*)(g_h + (size_t)(valid ? n : 0) * H);
        float* ar = At + le * 132;
        float4 z = make_float4(0.f, 0.f, 0.f, 0.f);
#pragma unroll
        for (int jj = 0; jj < 8; ++jj) { int j = q + jj * 4; *(float4*)(ar + j * 4) = valid ? hr[j] : z; }
    }
    // gemm_acc's leading __syncthreads covers At visibility

    int ti = tx >> 4, tj = tx & 15;
    int e0 = ti * 4, c0 = tj * 8;
    const float* Ws[5] = {Wg1, Wg1 + 128 * 128, Wa1, Wa1 + 128 * 128, Wm1};
    float* Os[5];
    Os[0] = g_Pgd; Os[1] = g_Pgs; Os[2] = g_Pad; Os[3] = g_Pas; Os[4] = g_Pms;

    for (int p = 0; p < 5; ++p) {
        float acc[4][8];
#pragma unroll
        for (int er = 0; er < 4; ++er)
#pragma unroll
            for (int cj = 0; cj < 8; ++cj) acc[er][cj] = 0.0f;
        gemm_acc(At, 132, 0, Ws[p], 128, 0, 128, Wt, acc);
#pragma unroll
        for (int er = 0; er < 4; ++er) {
            int n = n_base + e0 + er;
            if (n < N) {
                float* po = Os[p] + (size_t)n * H + c0;
                *(float4*)po = make_float4(acc[er][0], acc[er][1], acc[er][2], acc[er][3]);
                *(float4*)(po + 4) = make_float4(acc[er][4], acc[er][5], acc[er][6], acc[er][7]);
            }
        }
    }
}

// ---------------- init: zero agg / denom / maxkey ----------------
__global__ __launch_bounds__(256) void init_kernel(int N)
{
    int i = blockIdx.x * 256 + threadIdx.x;
    if (i < N * H) g_agg[i] = 0.0f;
    if (i < N) { g_maxkey[i] = 0u; g_denom[i] = 0.0f; }
}

// ---------------- K2: per-edge MLPs (emb parts + second layers only) ----------------
__global__ __launch_bounds__(256, 2) void edge_kernel(
    const int* __restrict__ esrc, const int* __restrict__ edst,
    const float* __restrict__ emb,
    const float* __restrict__ Wm1, const float* __restrict__ bm1,
    const float* __restrict__ Wm2, const float* __restrict__ bm2,
    const float* __restrict__ Wa1, const float* __restrict__ ba1,
    const float* __restrict__ Wa2, const float* __restrict__ ba2,
    const float* __restrict__ Wg1, const float* __restrict__ bg1,
    const float* __restrict__ Wg2, const float* __restrict__ bg2,
    int E)
{
    extern __shared__ float sm[];
    float* Hm    = sm;                 // [64][132] hidden buffer        (8448 f)
    float* Fe    = Hm + 64 * 132;      // [64][68]  edge_emb tile        (4352 f)
    float* Wt    = Fe + 64 * 68;       // [32][128] weight tile          (4096 f)
    float* gateS = Wt + 32 * 128;      // [64]                           (64 f)
    int*   sidx  = (int*)(gateS + 64); // [64]                           (64 w)
    int*   didx  = sidx + 64;          // [64]                           (64 w)

    int tx = threadIdx.x;
    int e_base = blockIdx.x * 64;

    if (tx < 64) {
        int e = e_base + tx;
        sidx[tx] = (e < E) ? esrc[e] : 0;
        didx[tx] = (e < E) ? edst[e] : 0;
    }
    { // gather edge_emb: 4 threads per edge, 4 float4 each
        int le = tx >> 2, q = tx & 3;
        int e = e_base + le;
        bool valid = e < E;
        const float4* em4 = (const float4*)(emb + (size_t)e * ED);
        float4 z = make_float4(0.f, 0.f, 0.f, 0.f);
        float* fr = Fe + le * 68;
#pragma unroll
        for (int jj = 0; jj < 4; ++jj) { int j = q + jj * 4; *(float4*)(fr + j * 4) = valid ? em4[j] : z; }
    }
    __syncthreads();

    int ti = tx >> 4, tj = tx & 15;
    int e0 = ti * 4, c0 = tj * 8;
    float acc[4][8];
    int srcs[4], dsts[4];
#pragma unroll
    for (int er = 0; er < 4; ++er) { srcs[er] = sidx[e0 + er]; dsts[er] = didx[e0 + er]; }

    // ---- gate path: gelu(Pgd[dst]+Pgs[src]+emb@Wg1_emb+bg1) @ Wg2 -> sigmoid
    load_acc_pp(acc, g_Pgd, g_Pgs, dsts, srcs, bg1, c0);
    gemm_acc(Fe, 68, 0, Wg1 + (size_t)256 * 128, 128, 0, 64, Wt, acc);
    store_hidden_gelu(acc, Hm, 132, e0, c0);
    __syncthreads();
    { // 4 threads per row: 32 MACs each + quad shfl reduce
        int row = tx >> 2, q = tx & 3;
        const float* hr = Hm + row * 132 + q * 32;
        const float* w  = Wg2 + q * 32;
        float s = 0.f;
#pragma unroll 8
        for (int c = 0; c < 32; ++c) s = fmaf(hr[c], w[c], s);
        s += __shfl_xor_sync(0xffffffffu, s, 1);
        s += __shfl_xor_sync(0xffffffffu, s, 2);
        if (q == 0) gateS[row] = 1.0f / (1.0f + expf(-(s + bg2[0])));
    }
    // no extra sync needed: next gemm_acc's leading sync separates dot reads
    // of Hm from its later overwrite (writes occur after that sync).

    // ---- attn path
    load_acc_pp(acc, g_Pad, g_Pas, dsts, srcs, ba1, c0);
    gemm_acc(Fe, 68, 0, Wa1 + (size_t)256 * 128, 128, 0, 64, Wt, acc);
    store_hidden_gelu(acc, Hm, 132, e0, c0);
    __syncthreads();
    {
        int row = tx >> 2, q = tx & 3;
        const float* hr = Hm + row * 132 + q * 32;
        const float* w  = Wa2 + q * 32;
        float s = 0.f;
#pragma unroll 8
        for (int c = 0; c < 32; ++c) s = fmaf(hr[c], w[c], s);
        s += __shfl_xor_sync(0xffffffffu, s, 1);
        s += __shfl_xor_sync(0xffffffffu, s, 2);
        int e = e_base + row;
        if (q == 0 && e < E) g_score[e] = s + ba2[0];
    }

    // ---- msg path: gelu(Pms[src]+emb@Wm1_emb+bm1) @ Wm2 + bm2, then * gate
    load_acc_p(acc, g_Pms, srcs, bm1, c0);
    gemm_acc(Fe, 68, 0, Wm1 + (size_t)128 * 128, 128, 0, 64, Wt, acc);
    store_hidden_gelu(acc, Hm, 132, e0, c0);
    init_acc_bias(acc, bm2 + c0);
    gemm_acc(Hm, 132, 0, Wm2, 128, 0, 128, Wt, acc);
#pragma unroll
    for (int er = 0; er < 4; ++er) {
        int e = e_base + e0 + er;
        if (e < E) {
            float g = gateS[e0 + er];
            float4 v0 = make_float4(acc[er][0] * g, acc[er][1] * g, acc[er][2] * g, acc[er][3] * g);
            float4 v1 = make_float4(acc[er][4] * g, acc[er][5] * g, acc[er][6] * g, acc[er][7] * g);
            float* mr = g_msg + (size_t)e * H + c0;
            *(float4*)mr = v0;
            *(float4*)(mr + 4) = v1;
        }
    }
}

// ---------------- K3: segment softmax ----------------
__global__ __launch_bounds__(256) void smax_kernel(const int* __restrict__ edst, int E)
{
    int e = blockIdx.x * 256 + threadIdx.x;
    if (e >= E) return;
    int i = __float_as_int(g_score[e]);
    unsigned key = (i >= 0) ? ((unsigned)i ^ 0x80000000u) : ~(unsigned)i;
    atomicMax(&g_maxkey[edst[e]], key);
}

__global__ __launch_bounds__(256) void exps_kernel(const int* __restrict__ edst, int E)
{
    int e = blockIdx.x * 256 + threadIdx.x;
    if (e >= E) return;
    int d = edst[e];
    unsigned k = g_maxkey[d];
    int bits = (k & 0x80000000u) ? (int)(k ^ 0x80000000u) : (int)~k;
    float m = __int_as_float(bits);
    float v = expf(g_score[e] - m);
    g_exp[e] = v;
    atomicAdd(&g_denom[d], v);
}

// ---------------- K4: edge_repr + scatter-add agg ----------------
__global__ __launch_bounds__(256) void scatter_kernel(
    const int* __restrict__ edst, float* __restrict__ erep, int E)
{
    int idx = blockIdx.x * 256 + threadIdx.x;
    int e = idx >> 5;
    if (e >= E) return;
    int l4 = idx & 31;
    int d = edst[e];
    float w = g_exp[e] / fmaxf(g_denom[d], 1e-12f);
    float4 m = ((const float4*)(g_msg + (size_t)e * H))[l4];
    float4 r = make_float4(m.x * w, m.y * w, m.z * w, m.w * w);
    ((float4*)(erep + (size_t)e * H))[l4] = r;
    float* ag = g_agg + (size_t)d * H + (size_t)l4 * 4;
    atomicAdd(ag + 0, r.x);
    atomicAdd(ag + 1, r.y);
    atomicAdd(ag + 2, r.z);
    atomicAdd(ag + 3, r.w);
}

// ---------------- K5: node update + LN2 + FFN ----------------
__global__ __launch_bounds__(256, 1) void node_kernel(
    const float* __restrict__ x,
    const float* __restrict__ Wself, const float* __restrict__ bself,
    const float* __restrict__ Wagg, const float* __restrict__ bagg,
    const float* __restrict__ g2, const float* __restrict__ b2,
    const float* __restrict__ Wf1, const float* __restrict__ bf1,
    const float* __restrict__ Wf2, const float* __restrict__ bf2,
    float* __restrict__ out, int N)
{
    extern __shared__ float sm[];
    float* At   = sm;                  // [64][132] A operand
    float* Ot   = At + 64 * 132;       // [64][132] out1 (pre-LN residual)
    float* H2   = Ot + 64 * 132;       // [64][260] FFN hidden
    float* Wt   = H2 + 64 * 260;       // [32][128]
    float* mu   = Wt + 32 * 128;       // [64]
    float* rstd = mu + 64;             // [64]

    int tx = threadIdx.x;
    int n_base = blockIdx.x * 64;
    int ti = tx >> 4, tj = tx & 15;
    int e0 = ti * 4, c0 = tj * 8;
    float acc[4][8];

    { // gather h
        int le = tx >> 2, q = tx & 3;
        int n = n_base + le;
        bool valid = n < N;
        const float4* hr = (const float4*)(g_h + (size_t)(valid ? n : 0) * H);
        float* ar = At + le * 132;
        float4 z = make_float4(0.f, 0.f, 0.f, 0.f);
#pragma unroll
        for (int jj = 0; jj < 8; ++jj) { int j = q + jj * 4; *(float4*)(ar + j * 4) = valid ? hr[j] : z; }
    }

    { // acc = bself + bagg
        float4 a0 = *(const float4*)(bself + c0), a1 = *(const float4*)(bself + c0 + 4);
        float4 g0 = *(const float4*)(bagg + c0),  g1 = *(const float4*)(bagg + c0 + 4);
        float bv[8] = {a0.x + g0.x, a0.y + g0.y, a0.z + g0.z, a0.w + g0.w,
                       a1.x + g1.x, a1.y + g1.y, a1.z + g1.z, a1.w + g1.w};
#pragma unroll
        for (int er = 0; er < 4; ++er)
#pragma unroll
            for (int cj = 0; cj < 8; ++cj) acc[er][cj] = bv[cj];
    }
    gemm_acc(At, 132, 0, Wself, 128, 0, 128, Wt, acc);

    { // overwrite At with agg (gemm_acc's trailing sync makes this safe)
        int le = tx >> 2, q = tx & 3;
        int n = n_base + le;
        bool valid = n < N;
        const float4* gr = (const float4*)(g_agg + (size_t)(valid ? n : 0) * H);
        float* ar = At + le * 132;
        float4 z = make_float4(0.f, 0.f, 0.f, 0.f);
#pragma unroll
        for (int jj = 0; jj < 8; ++jj) { int j = q + jj * 4; *(float4*)(ar + j * 4) = valid ? gr[j] : z; }
    }
    gemm_acc(At, 132, 0, Wagg, 128, 0, 128, Wt, acc);

    // out1 = x + update -> Ot
#pragma unroll
    for (int er = 0; er < 4; ++er) {
        int n = n_base + e0 + er;
        float4 x0 = make_float4(0.f, 0.f, 0.f, 0.f), x1 = x0;
        if (n < N) {
            x0 = *(const float4*)(x + (size_t)n * H + c0);
            x1 = *(const float4*)(x + (size_t)n * H + c0 + 4);
        }
        float4 o0 = make_float4(acc[er][0] + x0.x, acc[er][1] + x0.y, acc[er][2] + x0.z, acc[er][3] + x0.w);
        float4 o1 = make_float4(acc[er][4] + x1.x, acc[er][5] + x1.y, acc[er][6] + x1.z, acc[er][7] + x1.w);
        float* orow = Ot + (e0 + er) * 132 + c0;
        *(float4*)orow = o0;
        *(float4*)(orow + 4) = o1;
    }
    __syncthreads();

    // LN2 stats: 4 threads per row, single pass
    {
        int row = tx >> 2, q = tx & 3;
        const float* orow = Ot + row * 132 + q * 32;
        float s = 0.f, s2 = 0.f;
#pragma unroll 8
        for (int c = 0; c < 32; ++c) { float v = orow[c]; s += v; s2 = fmaf(v, v, s2); }
        s  += __shfl_xor_sync(0xffffffffu, s, 1);
        s  += __shfl_xor_sync(0xffffffffu, s, 2);
        s2 += __shfl_xor_sync(0xffffffffu, s2, 1);
        s2 += __shfl_xor_sync(0xffffffffu, s2, 2);
        if (q == 0) {
            float m = s * (1.0f / 128.0f);
            mu[row] = m;
            rstd[row] = rsqrtf(fmaxf(s2 * (1.0f / 128.0f) - m * m, 0.0f) + 1e-5f);
        }
    }
    __syncthreads();

    { // normalize -> At
        int le = tx & 63, cb = tx >> 6;
        float m = mu[le], r = rstd[le];
        const float* orow = Ot + le * 132;
        float* ar = At + le * 132;
#pragma unroll 4
        for (int c = cb * 32; c < cb * 32 + 32; ++c)
            ar[c] = (orow[c] - m) * r * g2[c] + b2[c];
    }

    // FFN layer 1: [64][128] @ [128][256] in two 128-col chunks
    for (int chunk = 0; chunk < 2; ++chunk) {
        int coff = chunk * 128;
        init_acc_bias(acc, bf1 + coff + c0);
        gemm_acc(At, 132, 0, Wf1, 256, coff, 128, Wt, acc);
        store_hidden_gelu(acc, H2 + coff, 260, e0, c0);
    }

    // FFN layer 2: [64][256] @ [256][128], + residual -> out
    init_acc_bias(acc, bf2 + c0);
    gemm_acc(H2, 260, 0, Wf2, 128, 0, 256, Wt, acc);
#pragma unroll
    for (int er = 0; er < 4; ++er) {
        int n = n_base + e0 + er;
        if (n < N) {
            const float* orow = Ot + (e0 + er) * 132 + c0;
            float4 o0 = make_float4(orow[0] + acc[er][0], orow[1] + acc[er][1],
                                    orow[2] + acc[er][2], orow[3] + acc[er][3]);
            float4 o1 = make_float4(orow[4] + acc[er][4], orow[5] + acc[er][5],
                                    orow[6] + acc[er][6], orow[7] + acc[er][7]);
            float* po = out + (size_t)n * H + c0;
            *(float4*)po = o0;
            *(float4*)(po + 4) = o1;
        }
    }
}

// ---------------- launch ----------------
extern "C" void kernel_launch(void* const* d_in, const int* in_sizes, int n_in,
                              void* d_out, int out_size)
{
    const float* x     = (const float*)d_in[0];
    const int*   esrc  = (const int*)d_in[1];
    const int*   edst  = (const int*)d_in[2];
    const float* emb   = (const float*)d_in[3];
    const float* ln1g  = (const float*)d_in[4];
    const float* ln1b  = (const float*)d_in[5];
    const float* ln2g  = (const float*)d_in[6];
    const float* ln2b  = (const float*)d_in[7];
    const float* Wself = (const float*)d_in[8];
    const float* bself = (const float*)d_in[9];
    const float* Wm1   = (const float*)d_in[10];
    const float* bm1   = (const float*)d_in[11];
    const float* Wm2   = (const float*)d_in[12];
    const float* bm2   = (const float*)d_in[13];
    const float* Wa1   = (const float*)d_in[14];
    const float* ba1   = (const float*)d_in[15];
    const float* Wa2   = (const float*)d_in[16];
    const float* ba2   = (const float*)d_in[17];
    const float* Wg1   = (const float*)d_in[18];
    const float* bg1   = (const float*)d_in[19];
    const float* Wg2   = (const float*)d_in[20];
    const float* bg2   = (const float*)d_in[21];
    const float* Wagg  = (const float*)d_in[22];
    const float* bagg  = (const float*)d_in[23];
    const float* Wf1   = (const float*)d_in[24];
    const float* bf1   = (const float*)d_in[25];
    const float* Wf2   = (const float*)d_in[26];
    const float* bf2   = (const float*)d_in[27];

    int N = in_sizes[0] / H;
    int E = in_sizes[1];

    float* out_nodes = (float*)d_out;
    float* out_edges = out_nodes + (size_t)N * H;

    const int PRE_SMEM  = (64 * 132 + 32 * 128) * 4;                        // 50176
    const int EDGE_SMEM = (64 * 132 + 64 * 68 + 32 * 128 + 64 + 128) * 4;   // 68352 (gateS + sidx[64] + didx[64])
    const int NODE_SMEM = (64 * 132 * 2 + 64 * 260 + 32 * 128 + 128) * 4;   // 151040
    cudaFuncSetAttribute(pre_kernel,  cudaFuncAttributeMaxDynamicSharedMemorySize, PRE_SMEM);
    cudaFuncSetAttribute(edge_kernel, cudaFuncAttributeMaxDynamicSharedMemorySize, EDGE_SMEM);
    cudaFuncSetAttribute(node_kernel, cudaFuncAttributeMaxDynamicSharedMemorySize, NODE_SMEM);

    float* hbuf;
    cudaGetSymbolAddress((void**)&hbuf, g_h);

    ln1_kernel<<<(N + 7) / 8, 256>>>(x, ln1g, ln1b, hbuf, N);
    pre_kernel<<<(N + 63) / 64, 256, PRE_SMEM>>>(Wg1, Wa1, Wm1, N);
    init_kernel<<<(N * H + 255) / 256, 256>>>(N);
    edge_kernel<<<(E + 63) / 64, 256, EDGE_SMEM>>>(
        esrc, edst, emb, Wm1, bm1, Wm2, bm2, Wa1, ba1, Wa2, ba2,
        Wg1, bg1, Wg2, bg2, E);
    smax_kernel<<<(E + 255) / 256, 256>>>(edst, E);
    exps_kernel<<<(E + 255) / 256, 256>>>(edst, E);
    scatter_kernel<<<((size_t)E * 32 + 255) / 256, 256>>>(edst, out_edges, E);
    node_kernel<<<(N + 63) / 64, 256, NODE_SMEM>>>(
        x, Wself, bself, Wagg, bagg, ln2g, ln2b, Wf1, bf1, Wf2, bf2,
        out_nodes, N);
}

// round 10
// speedup vs baseline: 3.7493x; 1.3752x over previous
#include <cuda_runtime.h>
#include <math.h>

#define H   128
#define ED  64
#define MAXN 100000
#define MAXE 500000

// ---------------- scratch (device globals; no allocations allowed) ----------------
__device__ float    g_h[(size_t)MAXN * H];      // LN1 output
__device__ float    g_msg[(size_t)MAXE * H];    // gated messages
__device__ float    g_score[MAXE];              // attention scores
__device__ float    g_exp[MAXE];                // exp(score - max)
__device__ unsigned g_maxkey[MAXN];             // ordered-uint segment max
__device__ float    g_denom[MAXN];              // segment sum of exp
__device__ float    g_agg[(size_t)MAXN * H];    // aggregated messages
// node-level precomputed first-layer partials (no bias)
__device__ float    g_Pgd[(size_t)MAXN * H];    // h @ Wg1[0:128]    (dst part, gate)
__device__ float    g_Pgs[(size_t)MAXN * H];    // h @ Wg1[128:256]  (src part, gate)
__device__ float    g_Pad[(size_t)MAXN * H];    // h @ Wa1[0:128]    (dst part, attn)
__device__ float    g_Pas[(size_t)MAXN * H];    // h @ Wa1[128:256]  (src part, attn)
__device__ float    g_Pms[(size_t)MAXN * H];    // h @ Wm1[0:128]    (src part, msg)

// ---------------- helpers ----------------
__device__ __forceinline__ float gelu_exact(float v) {
    return 0.5f * v * (1.0f + erff(v * 0.70710678118654752440f));
}

// C[64 rows][128 cols] += A[64][K] * W[K][128]; A in smem (row stride lda),
// W streamed from global through a 32x128 smem tile. 256 threads = 8 warps.
// Warp w: rows w*8..w*8+7. Lane l: cols l*4..l*4+3. acc[8][4] per thread.
// A loads are float4 (4 k-steps at once, broadcast); B loads one LDS.128/lane.
__device__ __forceinline__ void gemm_acc(
    const float* __restrict__ As, int lda,
    const float* __restrict__ Wg, int ldW, int woff,
    int K, float* __restrict__ Wts, float acc[8][4])
{
    int tx = threadIdx.x;
    int r0 = (tx >> 5) * 8;
    int c0 = (tx & 31) * 4;
    const float* abase = As + r0 * lda;

    for (int kt = 0; kt < K; kt += 32) {
        __syncthreads();
#pragma unroll
        for (int i = 0; i < 4; ++i) {
            int f4 = tx + i * 256;          // 1024 float4 = 32x128 tile
            int r  = f4 >> 5;
            int c  = (f4 & 31) << 2;
            *(float4*)(Wts + r * 128 + c) =
                *(const float4*)(Wg + (size_t)(kt + r) * ldW + woff + c);
        }
        __syncthreads();
#pragma unroll
        for (int kk4 = 0; kk4 < 32; kk4 += 4) {
            float4 b0 = *(const float4*)(Wts + (kk4 + 0) * 128 + c0);
            float4 b1 = *(const float4*)(Wts + (kk4 + 1) * 128 + c0);
            float4 b2 = *(const float4*)(Wts + (kk4 + 2) * 128 + c0);
            float4 b3 = *(const float4*)(Wts + (kk4 + 3) * 128 + c0);
#pragma unroll
            for (int er = 0; er < 8; ++er) {
                float4 a = *(const float4*)(abase + er * lda + kt + kk4);
                acc[er][0] = fmaf(a.x, b0.x, acc[er][0]);
                acc[er][1] = fmaf(a.x, b0.y, acc[er][1]);
                acc[er][2] = fmaf(a.x, b0.z, acc[er][2]);
                acc[er][3] = fmaf(a.x, b0.w, acc[er][3]);
                acc[er][0] = fmaf(a.y, b1.x, acc[er][0]);
                acc[er][1] = fmaf(a.y, b1.y, acc[er][1]);
                acc[er][2] = fmaf(a.y, b1.z, acc[er][2]);
                acc[er][3] = fmaf(a.y, b1.w, acc[er][3]);
                acc[er][0] = fmaf(a.z, b2.x, acc[er][0]);
                acc[er][1] = fmaf(a.z, b2.y, acc[er][1]);
                acc[er][2] = fmaf(a.z, b2.z, acc[er][2]);
                acc[er][3] = fmaf(a.z, b2.w, acc[er][3]);
                acc[er][0] = fmaf(a.w, b3.x, acc[er][0]);
                acc[er][1] = fmaf(a.w, b3.y, acc[er][1]);
                acc[er][2] = fmaf(a.w, b3.z, acc[er][2]);
                acc[er][3] = fmaf(a.w, b3.w, acc[er][3]);
            }
        }
    }
    __syncthreads();
}

// b4 must already point at this thread's 4 columns (base + c0)
__device__ __forceinline__ void init_acc_bias(float acc[8][4], const float* __restrict__ b4) {
    float4 bv = *(const float4*)b4;
#pragma unroll
    for (int er = 0; er < 8; ++er) {
        acc[er][0] = bv.x; acc[er][1] = bv.y; acc[er][2] = bv.z; acc[er][3] = bv.w;
    }
}

// acc = Pd[dst] + Ps[src] + bias  (per-thread float4 cells, from global/L2)
__device__ __forceinline__ void load_acc_pp(
    float acc[8][4], const float* __restrict__ Pd, const float* __restrict__ Ps,
    const int* dsts, const int* srcs, const float* __restrict__ b, int c0)
{
    float4 bv = *(const float4*)(b + c0);
#pragma unroll
    for (int er = 0; er < 8; ++er) {
        float4 d0 = *(const float4*)(Pd + (size_t)dsts[er] * H + c0);
        float4 s0 = *(const float4*)(Ps + (size_t)srcs[er] * H + c0);
        acc[er][0] = d0.x + s0.x + bv.x;
        acc[er][1] = d0.y + s0.y + bv.y;
        acc[er][2] = d0.z + s0.z + bv.z;
        acc[er][3] = d0.w + s0.w + bv.w;
    }
}

// acc = Ps[src] + bias
__device__ __forceinline__ void load_acc_p(
    float acc[8][4], const float* __restrict__ Ps,
    const int* srcs, const float* __restrict__ b, int c0)
{
    float4 bv = *(const float4*)(b + c0);
#pragma unroll
    for (int er = 0; er < 8; ++er) {
        float4 s0 = *(const float4*)(Ps + (size_t)srcs[er] * H + c0);
        acc[er][0] = s0.x + bv.x;
        acc[er][1] = s0.y + bv.y;
        acc[er][2] = s0.z + bv.z;
        acc[er][3] = s0.w + bv.w;
    }
}

__device__ __forceinline__ void store_hidden_gelu(float acc[8][4], float* __restrict__ Hm,
                                                  int stride, int r0, int c0) {
#pragma unroll
    for (int er = 0; er < 8; ++er) {
        float4 v = make_float4(gelu_exact(acc[er][0]), gelu_exact(acc[er][1]),
                               gelu_exact(acc[er][2]), gelu_exact(acc[er][3]));
        *(float4*)(Hm + (r0 + er) * stride + c0) = v;
    }
}

// ---------------- K1: LayerNorm1 ----------------
__global__ __launch_bounds__(256) void ln1_kernel(
    const float* __restrict__ x, const float* __restrict__ g,
    const float* __restrict__ b, float* __restrict__ hout, int N)
{
    int node = blockIdx.x * 8 + (threadIdx.x >> 5);
    if (node >= N) return;
    int lane = threadIdx.x & 31;
    float4 v = ((const float4*)(x + (size_t)node * H))[lane];
    float s = v.x + v.y + v.z + v.w;
#pragma unroll
    for (int o = 16; o; o >>= 1) s += __shfl_xor_sync(0xffffffffu, s, o);
    float m = s * (1.0f / 128.0f);
    float dx = v.x - m, dy = v.y - m, dz = v.z - m, dw = v.w - m;
    float ss = dx * dx + dy * dy + dz * dz + dw * dw;
#pragma unroll
    for (int o = 16; o; o >>= 1) ss += __shfl_xor_sync(0xffffffffu, ss, o);
    float r = rsqrtf(ss * (1.0f / 128.0f) + 1e-5f);
    float4 gv = ((const float4*)g)[lane], bv = ((const float4*)b)[lane];
    float4 o4 = make_float4(dx * r * gv.x + bv.x, dy * r * gv.y + bv.y,
                            dz * r * gv.z + bv.z, dw * r * gv.w + bv.w);
    ((float4*)(hout + (size_t)node * H))[lane] = o4;
}

// ---------------- K1b: node-level precompute of first-layer partials ----------------
__global__ __launch_bounds__(256, 2) void pre_kernel(
    const float* __restrict__ Wg1, const float* __restrict__ Wa1,
    const float* __restrict__ Wm1, int N)
{
    extern __shared__ float sm[];
    float* At = sm;                 // [64][132]
    float* Wt = At + 64 * 132;      // [32][128]

    int tx = threadIdx.x;
    int n_base = blockIdx.x * 64;
    { // gather h tile
        int le = tx >> 2, q = tx & 3;
        int n = n_base + le;
        bool valid = n < N;
        const float4* hr = (const float4*)(g_h + (size_t)(valid ? n : 0) * H);
        float* ar = At + le * 132;
        float4 z = make_float4(0.f, 0.f, 0.f, 0.f);
#pragma unroll
        for (int jj = 0; jj < 8; ++jj) { int j = q + jj * 4; *(float4*)(ar + j * 4) = valid ? hr[j] : z; }
    }
    // gemm_acc's leading __syncthreads covers At visibility

    int r0 = (tx >> 5) * 8;
    int c0 = (tx & 31) * 4;
    const float* Ws[5] = {Wg1, Wg1 + 128 * 128, Wa1, Wa1 + 128 * 128, Wm1};
    float* Os[5];
    Os[0] = g_Pgd; Os[1] = g_Pgs; Os[2] = g_Pad; Os[3] = g_Pas; Os[4] = g_Pms;

    for (int p = 0; p < 5; ++p) {
        float acc[8][4];
#pragma unroll
        for (int er = 0; er < 8; ++er)
#pragma unroll
            for (int cj = 0; cj < 4; ++cj) acc[er][cj] = 0.0f;
        gemm_acc(At, 132, Ws[p], 128, 0, 128, Wt, acc);
#pragma unroll
        for (int er = 0; er < 8; ++er) {
            int n = n_base + r0 + er;
            if (n < N) {
                *(float4*)(Os[p] + (size_t)n * H + c0) =
                    make_float4(acc[er][0], acc[er][1], acc[er][2], acc[er][3]);
            }
        }
    }
}

// ---------------- init: zero agg / denom / maxkey ----------------
__global__ __launch_bounds__(256) void init_kernel(int N)
{
    int i = blockIdx.x * 256 + threadIdx.x;
    if (i < N * H) g_agg[i] = 0.0f;
    if (i < N) { g_maxkey[i] = 0u; g_denom[i] = 0.0f; }
}

// ---------------- K2: per-edge MLPs (emb parts + second layers only) ----------------
__global__ __launch_bounds__(256, 2) void edge_kernel(
    const int* __restrict__ esrc, const int* __restrict__ edst,
    const float* __restrict__ emb,
    const float* __restrict__ Wm1, const float* __restrict__ bm1,
    const float* __restrict__ Wm2, const float* __restrict__ bm2,
    const float* __restrict__ Wa1, const float* __restrict__ ba1,
    const float* __restrict__ Wa2, const float* __restrict__ ba2,
    const float* __restrict__ Wg1, const float* __restrict__ bg1,
    const float* __restrict__ Wg2, const float* __restrict__ bg2,
    int E)
{
    extern __shared__ float sm[];
    float* Hm    = sm;                 // [64][132] hidden buffer
    float* Fe    = Hm + 64 * 132;      // [64][68]  edge_emb tile
    float* Wt    = Fe + 64 * 68;       // [32][128] weight tile
    float* gateS = Wt + 32 * 128;      // [64]
    int*   sidx  = (int*)(gateS + 64); // [64]
    int*   didx  = sidx + 64;          // [64]

    int tx = threadIdx.x;
    int e_base = blockIdx.x * 64;

    if (tx < 64) {
        int e = e_base + tx;
        sidx[tx] = (e < E) ? esrc[e] : 0;
        didx[tx] = (e < E) ? edst[e] : 0;
    }
    { // gather edge_emb: 4 threads per edge, 4 float4 each
        int le = tx >> 2, q = tx & 3;
        int e = e_base + le;
        bool valid = e < E;
        const float4* em4 = (const float4*)(emb + (size_t)e * ED);
        float4 z = make_float4(0.f, 0.f, 0.f, 0.f);
        float* fr = Fe + le * 68;
#pragma unroll
        for (int jj = 0; jj < 4; ++jj) { int j = q + jj * 4; *(float4*)(fr + j * 4) = valid ? em4[j] : z; }
    }
    __syncthreads();

    int r0 = (tx >> 5) * 8;
    int c0 = (tx & 31) * 4;
    float acc[8][4];
    int srcs[8], dsts[8];
#pragma unroll
    for (int er = 0; er < 8; ++er) { srcs[er] = sidx[r0 + er]; dsts[er] = didx[r0 + er]; }

    // ---- gate path: gelu(Pgd[dst]+Pgs[src]+emb@Wg1_emb+bg1) @ Wg2 -> sigmoid
    load_acc_pp(acc, g_Pgd, g_Pgs, dsts, srcs, bg1, c0);
    gemm_acc(Fe, 68, Wg1 + (size_t)256 * 128, 128, 0, 64, Wt, acc);
    store_hidden_gelu(acc, Hm, 132, r0, c0);
    __syncthreads();
    { // 4 threads per row: 32 MACs each + quad shfl reduce
        int row = tx >> 2, q = tx & 3;
        const float* hr = Hm + row * 132 + q * 32;
        const float* w  = Wg2 + q * 32;
        float s = 0.f;
#pragma unroll 8
        for (int c = 0; c < 32; ++c) s = fmaf(hr[c], w[c], s);
        s += __shfl_xor_sync(0xffffffffu, s, 1);
        s += __shfl_xor_sync(0xffffffffu, s, 2);
        if (q == 0) gateS[row] = 1.0f / (1.0f + expf(-(s + bg2[0])));
    }
    // no extra sync needed: next gemm_acc's leading sync separates dot reads
    // of Hm from its later overwrite (writes occur after that sync).

    // ---- attn path
    load_acc_pp(acc, g_Pad, g_Pas, dsts, srcs, ba1, c0);
    gemm_acc(Fe, 68, Wa1 + (size_t)256 * 128, 128, 0, 64, Wt, acc);
    store_hidden_gelu(acc, Hm, 132, r0, c0);
    __syncthreads();
    {
        int row = tx >> 2, q = tx & 3;
        const float* hr = Hm + row * 132 + q * 32;
        const float* w  = Wa2 + q * 32;
        float s = 0.f;
#pragma unroll 8
        for (int c = 0; c < 32; ++c) s = fmaf(hr[c], w[c], s);
        s += __shfl_xor_sync(0xffffffffu, s, 1);
        s += __shfl_xor_sync(0xffffffffu, s, 2);
        int e = e_base + row;
        if (q == 0 && e < E) g_score[e] = s + ba2[0];
    }

    // ---- msg path: gelu(Pms[src]+emb@Wm1_emb+bm1) @ Wm2 + bm2, then * gate
    load_acc_p(acc, g_Pms, srcs, bm1, c0);
    gemm_acc(Fe, 68, Wm1 + (size_t)128 * 128, 128, 0, 64, Wt, acc);
    store_hidden_gelu(acc, Hm, 132, r0, c0);
    init_acc_bias(acc, bm2 + c0);
    gemm_acc(Hm, 132, Wm2, 128, 0, 128, Wt, acc);
#pragma unroll
    for (int er = 0; er < 8; ++er) {
        int e = e_base + r0 + er;
        if (e < E) {
            float g = gateS[r0 + er];
            *(float4*)(g_msg + (size_t)e * H + c0) =
                make_float4(acc[er][0] * g, acc[er][1] * g, acc[er][2] * g, acc[er][3] * g);
        }
    }
}

// ---------------- K3: segment softmax ----------------
__global__ __launch_bounds__(256) void smax_kernel(const int* __restrict__ edst, int E)
{
    int e = blockIdx.x * 256 + threadIdx.x;
    if (e >= E) return;
    int i = __float_as_int(g_score[e]);
    unsigned key = (i >= 0) ? ((unsigned)i ^ 0x80000000u) : ~(unsigned)i;
    atomicMax(&g_maxkey[edst[e]], key);
}

__global__ __launch_bounds__(256) void exps_kernel(const int* __restrict__ edst, int E)
{
    int e = blockIdx.x * 256 + threadIdx.x;
    if (e >= E) return;
    int d = edst[e];
    unsigned k = g_maxkey[d];
    int bits = (k & 0x80000000u) ? (int)(k ^ 0x80000000u) : (int)~k;
    float m = __int_as_float(bits);
    float v = expf(g_score[e] - m);
    g_exp[e] = v;
    atomicAdd(&g_denom[d], v);
}

// ---------------- K4: edge_repr + scatter-add agg (vectorized red) ----------------
__global__ __launch_bounds__(256) void scatter_kernel(
    const int* __restrict__ edst, float* __restrict__ erep, int E)
{
    int idx = blockIdx.x * 256 + threadIdx.x;
    int e = idx >> 5;
    if (e >= E) return;
    int l4 = idx & 31;
    int d = edst[e];
    float w = g_exp[e] / fmaxf(g_denom[d], 1e-12f);
    float4 m = ((const float4*)(g_msg + (size_t)e * H))[l4];
    float4 r = make_float4(m.x * w, m.y * w, m.z * w, m.w * w);
    ((float4*)(erep + (size_t)e * H))[l4] = r;
    float* ag = g_agg + (size_t)d * H + (size_t)l4 * 4;
    asm volatile("red.global.add.v4.f32 [%0], {%1, %2, %3, %4};"
                 :: "l"(ag), "f"(r.x), "f"(r.y), "f"(r.z), "f"(r.w)
                 : "memory");
}

// ---------------- K5: node update + LN2 + FFN ----------------
__global__ __launch_bounds__(256, 1) void node_kernel(
    const float* __restrict__ x,
    const float* __restrict__ Wself, const float* __restrict__ bself,
    const float* __restrict__ Wagg, const float* __restrict__ bagg,
    const float* __restrict__ g2, const float* __restrict__ b2,
    const float* __restrict__ Wf1, const float* __restrict__ bf1,
    const float* __restrict__ Wf2, const float* __restrict__ bf2,
    float* __restrict__ out, int N)
{
    extern __shared__ float sm[];
    float* At   = sm;                  // [64][132] A operand
    float* Ot   = At + 64 * 132;       // [64][132] out1 (pre-LN residual)
    float* H2   = Ot + 64 * 132;       // [64][260] FFN hidden
    float* Wt   = H2 + 64 * 260;       // [32][128]
    float* mu   = Wt + 32 * 128;       // [64]
    float* rstd = mu + 64;             // [64]

    int tx = threadIdx.x;
    int n_base = blockIdx.x * 64;
    int r0 = (tx >> 5) * 8;
    int c0 = (tx & 31) * 4;
    float acc[8][4];

    { // gather h
        int le = tx >> 2, q = tx & 3;
        int n = n_base + le;
        bool valid = n < N;
        const float4* hr = (const float4*)(g_h + (size_t)(valid ? n : 0) * H);
        float* ar = At + le * 132;
        float4 z = make_float4(0.f, 0.f, 0.f, 0.f);
#pragma unroll
        for (int jj = 0; jj < 8; ++jj) { int j = q + jj * 4; *(float4*)(ar + j * 4) = valid ? hr[j] : z; }
    }

    { // acc = bself + bagg
        float4 a0 = *(const float4*)(bself + c0);
        float4 g0 = *(const float4*)(bagg + c0);
        float4 bv = make_float4(a0.x + g0.x, a0.y + g0.y, a0.z + g0.z, a0.w + g0.w);
#pragma unroll
        for (int er = 0; er < 8; ++er) {
            acc[er][0] = bv.x; acc[er][1] = bv.y; acc[er][2] = bv.z; acc[er][3] = bv.w;
        }
    }
    gemm_acc(At, 132, Wself, 128, 0, 128, Wt, acc);

    { // overwrite At with agg (gemm_acc's trailing sync makes this safe)
        int le = tx >> 2, q = tx & 3;
        int n = n_base + le;
        bool valid = n < N;
        const float4* gr = (const float4*)(g_agg + (size_t)(valid ? n : 0) * H);
        float* ar = At + le * 132;
        float4 z = make_float4(0.f, 0.f, 0.f, 0.f);
#pragma unroll
        for (int jj = 0; jj < 8; ++jj) { int j = q + jj * 4; *(float4*)(ar + j * 4) = valid ? gr[j] : z; }
    }
    gemm_acc(At, 132, Wagg, 128, 0, 128, Wt, acc);

    // out1 = x + update -> Ot
#pragma unroll
    for (int er = 0; er < 8; ++er) {
        int n = n_base + r0 + er;
        float4 x0 = make_float4(0.f, 0.f, 0.f, 0.f);
        if (n < N) x0 = *(const float4*)(x + (size_t)n * H + c0);
        *(float4*)(Ot + (r0 + er) * 132 + c0) =
            make_float4(acc[er][0] + x0.x, acc[er][1] + x0.y,
                        acc[er][2] + x0.z, acc[er][3] + x0.w);
    }
    __syncthreads();

    // LN2 stats: 4 threads per row, single pass
    {
        int row = tx >> 2, q = tx & 3;
        const float* orow = Ot + row * 132 + q * 32;
        float s = 0.f, s2 = 0.f;
#pragma unroll 8
        for (int c = 0; c < 32; ++c) { float v = orow[c]; s += v; s2 = fmaf(v, v, s2); }
        s  += __shfl_xor_sync(0xffffffffu, s, 1);
        s  += __shfl_xor_sync(0xffffffffu, s, 2);
        s2 += __shfl_xor_sync(0xffffffffu, s2, 1);
        s2 += __shfl_xor_sync(0xffffffffu, s2, 2);
        if (q == 0) {
            float m = s * (1.0f / 128.0f);
            mu[row] = m;
            rstd[row] = rsqrtf(fmaxf(s2 * (1.0f / 128.0f) - m * m, 0.0f) + 1e-5f);
        }
    }
    __syncthreads();

    { // normalize -> At
        int le = tx & 63, cb = tx >> 6;
        float m = mu[le], r = rstd[le];
        const float* orow = Ot + le * 132;
        float* ar = At + le * 132;
#pragma unroll 4
        for (int c = cb * 32; c < cb * 32 + 32; ++c)
            ar[c] = (orow[c] - m) * r * g2[c] + b2[c];
    }

    // FFN layer 1: [64][128] @ [128][256] in two 128-col chunks
    for (int chunk = 0; chunk < 2; ++chunk) {
        int coff = chunk * 128;
        init_acc_bias(acc, bf1 + coff + c0);
        gemm_acc(At, 132, Wf1, 256, coff, 128, Wt, acc);
        store_hidden_gelu(acc, H2 + coff, 260, r0, c0);
    }

    // FFN layer 2: [64][256] @ [256][128], + residual -> out
    init_acc_bias(acc, bf2 + c0);
    gemm_acc(H2, 260, Wf2, 128, 0, 256, Wt, acc);
#pragma unroll
    for (int er = 0; er < 8; ++er) {
        int n = n_base + r0 + er;
        if (n < N) {
            const float* orow = Ot + (r0 + er) * 132 + c0;
            *(float4*)(out + (size_t)n * H + c0) =
                make_float4(orow[0] + acc[er][0], orow[1] + acc[er][1],
                            orow[2] + acc[er][2], orow[3] + acc[er][3]);
        }
    }
}

// ---------------- launch ----------------
extern "C" void kernel_launch(void* const* d_in, const int* in_sizes, int n_in,
                              void* d_out, int out_size)
{
    const float* x     = (const float*)d_in[0];
    const int*   esrc  = (const int*)d_in[1];
    const int*   edst  = (const int*)d_in[2];
    const float* emb   = (const float*)d_in[3];
    const float* ln1g  = (const float*)d_in[4];
    const float* ln1b  = (const float*)d_in[5];
    const float* ln2g  = (const float*)d_in[6];
    const float* ln2b  = (const float*)d_in[7];
    const float* Wself = (const float*)d_in[8];
    const float* bself = (const float*)d_in[9];
    const float* Wm1   = (const float*)d_in[10];
    const float* bm1   = (const float*)d_in[11];
    const float* Wm2   = (const float*)d_in[12];
    const float* bm2   = (const float*)d_in[13];
    const float* Wa1   = (const float*)d_in[14];
    const float* ba1   = (const float*)d_in[15];
    const float* Wa2   = (const float*)d_in[16];
    const float* ba2   = (const float*)d_in[17];
    const float* Wg1   = (const float*)d_in[18];
    const float* bg1   = (const float*)d_in[19];
    const float* Wg2   = (const float*)d_in[20];
    const float* bg2   = (const float*)d_in[21];
    const float* Wagg  = (const float*)d_in[22];
    const float* bagg  = (const float*)d_in[23];
    const float* Wf1   = (const float*)d_in[24];
    const float* bf1   = (const float*)d_in[25];
    const float* Wf2   = (const float*)d_in[26];
    const float* bf2   = (const float*)d_in[27];

    int N = in_sizes[0] / H;
    int E = in_sizes[1];

    float* out_nodes = (float*)d_out;
    float* out_edges = out_nodes + (size_t)N * H;

    const int PRE_SMEM  = (64 * 132 + 32 * 128) * 4;                        // 50176
    const int EDGE_SMEM = (64 * 132 + 64 * 68 + 32 * 128 + 64 + 128) * 4;   // 68352
    const int NODE_SMEM = (64 * 132 * 2 + 64 * 260 + 32 * 128 + 128) * 4;   // 151040
    cudaFuncSetAttribute(pre_kernel,  cudaFuncAttributeMaxDynamicSharedMemorySize, PRE_SMEM);
    cudaFuncSetAttribute(edge_kernel, cudaFuncAttributeMaxDynamicSharedMemorySize, EDGE_SMEM);
    cudaFuncSetAttribute(node_kernel, cudaFuncAttributeMaxDynamicSharedMemorySize, NODE_SMEM);

    float* hbuf;
    cudaGetSymbolAddress((void**)&hbuf, g_h);

    ln1_kernel<<<(N + 7) / 8, 256>>>(x, ln1g, ln1b, hbuf, N);
    pre_kernel<<<(N + 63) / 64, 256, PRE_SMEM>>>(Wg1, Wa1, Wm1, N);
    init_kernel<<<(N * H + 255) / 256, 256>>>(N);
    edge_kernel<<<(E + 63) / 64, 256, EDGE_SMEM>>>(
        esrc, edst, emb, Wm1, bm1, Wm2, bm2, Wa1, ba1, Wa2, ba2,
        Wg1, bg1, Wg2, bg2, E);
    smax_kernel<<<(E + 255) / 256, 256>>>(edst, E);
    exps_kernel<<<(E + 255) / 256, 256>>>(edst, E);
    scatter_kernel<<<((size_t)E * 32 + 255) / 256, 256>>>(edst, out_edges, E);
    node_kernel<<<(N + 63) / 64, 256, NODE_SMEM>>>(
        x, Wself, bself, Wagg, bagg, ln2g, ln2b, Wf1, bf1, Wf2, bf2,
        out_nodes, N);
}

// round 12
// speedup vs baseline: 4.1713x; 1.1126x over previous
#include <cuda_runtime.h>
#include <math.h>

#define H   128
#define ED  64
#define MAXN 100000
#define MAXE 500000

// ---------------- scratch (device globals; no allocations allowed) ----------------
__device__ float    g_h[(size_t)MAXN * H];      // LN1 output
__device__ float    g_msg[(size_t)MAXE * H];    // gated messages
__device__ float    g_score[MAXE];              // attention scores
__device__ float    g_exp[MAXE];                // exp(score - max)
__device__ unsigned g_maxkey[MAXN];             // ordered-uint segment max
__device__ float    g_denom[MAXN];              // segment sum of exp
__device__ float    g_agg[(size_t)MAXN * H];    // aggregated messages
// node-level precomputed first-layer partials (no bias)
__device__ float    g_Pgd[(size_t)MAXN * H];    // h @ Wg1[0:128]    (dst part, gate)
__device__ float    g_Pgs[(size_t)MAXN * H];    // h @ Wg1[128:256]  (src part, gate)
__device__ float    g_Pad[(size_t)MAXN * H];    // h @ Wa1[0:128]    (dst part, attn)
__device__ float    g_Pas[(size_t)MAXN * H];    // h @ Wa1[128:256]  (src part, attn)
__device__ float    g_Pms[(size_t)MAXN * H];    // h @ Wm1[0:128]    (src part, msg)

// ---------------- helpers ----------------
__device__ __forceinline__ float gelu_exact(float v) {
    return 0.5f * v * (1.0f + erff(v * 0.70710678118654752440f));
}

__device__ __forceinline__ void cp16(float* dst, const float* src) {
    unsigned s = (unsigned)__cvta_generic_to_shared(dst);
    asm volatile("cp.async.cg.shared.global [%0], [%1], 16;" :: "r"(s), "l"(src) : "memory");
}
#define CP_COMMIT() asm volatile("cp.async.commit_group;" ::: "memory")
#define CP_WAIT0()  asm volatile("cp.async.wait_group 0;" ::: "memory")

// ---------------- templated tiled GEMM with cp.async double-buffered weights ----
// C[64 rows][128 cols] += A[64][K] * W[K][128]; A in smem (row stride LDA),
// W streamed global->smem via cp.async into Wts (2 buffers of 32x128).
// 256 threads = 8 warps. Warp w: rows w*8..w*8+7. Lane l: cols l*4..l*4+3.
// One __syncthreads per 32-k tile; weight-load latency hidden behind compute.
template<int K, int LDA, int LDW>
__device__ __forceinline__ void gemm_acc_t(
    const float* __restrict__ As,
    const float* __restrict__ Wg, int woff,
    float* __restrict__ Wts, float acc[8][4])
{
    constexpr int NT = K / 32;
    const int tx  = threadIdx.x;
    const int wid = tx >> 5;
    const int c0  = (tx & 31) * 4;
    const float* abase = As + (wid * 8) * LDA;
    const float* wptr  = Wg + (size_t)wid * LDW + woff + c0;   // row wid of tile
    float* s0 = Wts + wid * 128 + c0;                          // buf0 store slot

    // prologue: tile 0 -> buf0
#pragma unroll
    for (int i = 0; i < 4; ++i)
        cp16(s0 + i * 8 * 128, wptr + (size_t)(i * 8) * LDW);
    CP_COMMIT();
    CP_WAIT0();
    __syncthreads();      // tile0 visible; also orders caller's As writes

    int cur = 0;
#pragma unroll 1
    for (int t = 0; t < NT; ++t) {
        if (t + 1 < NT) {   // issue next tile into the other buffer (free since last sync)
            float* sn = s0 + (cur ? 0 : 4096);
            const float* wn = wptr + (size_t)((t + 1) * 32) * LDW;
#pragma unroll
            for (int i = 0; i < 4; ++i)
                cp16(sn + i * 8 * 128, wn + (size_t)(i * 8) * LDW);
            CP_COMMIT();
        }
        const float* wb = Wts + (cur ? 4096 : 0);
        const float* ab = abase + t * 32;
#pragma unroll
        for (int kk4 = 0; kk4 < 32; kk4 += 4) {
            float4 b0 = *(const float4*)(wb + (kk4 + 0) * 128 + c0);
            float4 b1 = *(const float4*)(wb + (kk4 + 1) * 128 + c0);
            float4 b2 = *(const float4*)(wb + (kk4 + 2) * 128 + c0);
            float4 b3 = *(const float4*)(wb + (kk4 + 3) * 128 + c0);
#pragma unroll
            for (int er = 0; er < 8; ++er) {
                float4 a = *(const float4*)(ab + er * LDA + kk4);
                acc[er][0] = fmaf(a.x, b0.x, acc[er][0]);
                acc[er][1] = fmaf(a.x, b0.y, acc[er][1]);
                acc[er][2] = fmaf(a.x, b0.z, acc[er][2]);
                acc[er][3] = fmaf(a.x, b0.w, acc[er][3]);
                acc[er][0] = fmaf(a.y, b1.x, acc[er][0]);
                acc[er][1] = fmaf(a.y, b1.y, acc[er][1]);
                acc[er][2] = fmaf(a.y, b1.z, acc[er][2]);
                acc[er][3] = fmaf(a.y, b1.w, acc[er][3]);
                acc[er][0] = fmaf(a.z, b2.x, acc[er][0]);
                acc[er][1] = fmaf(a.z, b2.y, acc[er][1]);
                acc[er][2] = fmaf(a.z, b2.z, acc[er][2]);
                acc[er][3] = fmaf(a.z, b2.w, acc[er][3]);
                acc[er][0] = fmaf(a.w, b3.x, acc[er][0]);
                acc[er][1] = fmaf(a.w, b3.y, acc[er][1]);
                acc[er][2] = fmaf(a.w, b3.z, acc[er][2]);
                acc[er][3] = fmaf(a.w, b3.w, acc[er][3]);
            }
        }
        if (t + 1 < NT) {
            CP_WAIT0();            // next tile landed (had whole compute to do so)
            __syncthreads();       // all warps done reading buf cur; next tile visible
            cur ^= 1;
        }
    }
    __syncthreads();   // protect Wts and As for the caller's next phase
}

// b4 must already point at this thread's 4 columns (base + c0)
__device__ __forceinline__ void init_acc_bias(float acc[8][4], const float* __restrict__ b4) {
    float4 bv = *(const float4*)b4;
#pragma unroll
    for (int er = 0; er < 8; ++er) {
        acc[er][0] = bv.x; acc[er][1] = bv.y; acc[er][2] = bv.z; acc[er][3] = bv.w;
    }
}

// acc = Pd[dst] + Ps[src] + bias  (per-thread float4 cells, from global/L2)
__device__ __forceinline__ void load_acc_pp(
    float acc[8][4], const float* __restrict__ Pd, const float* __restrict__ Ps,
    const int* dsts, const int* srcs, const float* __restrict__ b, int c0)
{
    float4 bv = *(const float4*)(b + c0);
#pragma unroll
    for (int er = 0; er < 8; ++er) {
        float4 d0 = *(const float4*)(Pd + (size_t)dsts[er] * H + c0);
        float4 s0 = *(const float4*)(Ps + (size_t)srcs[er] * H + c0);
        acc[er][0] = d0.x + s0.x + bv.x;
        acc[er][1] = d0.y + s0.y + bv.y;
        acc[er][2] = d0.z + s0.z + bv.z;
        acc[er][3] = d0.w + s0.w + bv.w;
    }
}

// acc = Ps[src] + bias
__device__ __forceinline__ void load_acc_p(
    float acc[8][4], const float* __restrict__ Ps,
    const int* srcs, const float* __restrict__ b, int c0)
{
    float4 bv = *(const float4*)(b + c0);
#pragma unroll
    for (int er = 0; er < 8; ++er) {
        float4 s0 = *(const float4*)(Ps + (size_t)srcs[er] * H + c0);
        acc[er][0] = s0.x + bv.x;
        acc[er][1] = s0.y + bv.y;
        acc[er][2] = s0.z + bv.z;
        acc[er][3] = s0.w + bv.w;
    }
}

__device__ __forceinline__ void store_hidden_gelu(float acc[8][4], float* __restrict__ Hm,
                                                  int stride, int r0, int c0) {
#pragma unroll
    for (int er = 0; er < 8; ++er) {
        float4 v = make_float4(gelu_exact(acc[er][0]), gelu_exact(acc[er][1]),
                               gelu_exact(acc[er][2]), gelu_exact(acc[er][3]));
        *(float4*)(Hm + (r0 + er) * stride + c0) = v;
    }
}

// ---------------- K1: LayerNorm1 ----------------
__global__ __launch_bounds__(256) void ln1_kernel(
    const float* __restrict__ x, const float* __restrict__ g,
    const float* __restrict__ b, float* __restrict__ hout, int N)
{
    int node = blockIdx.x * 8 + (threadIdx.x >> 5);
    if (node >= N) return;
    int lane = threadIdx.x & 31;
    float4 v = ((const float4*)(x + (size_t)node * H))[lane];
    float s = v.x + v.y + v.z + v.w;
#pragma unroll
    for (int o = 16; o; o >>= 1) s += __shfl_xor_sync(0xffffffffu, s, o);
    float m = s * (1.0f / 128.0f);
    float dx = v.x - m, dy = v.y - m, dz = v.z - m, dw = v.w - m;
    float ss = dx * dx + dy * dy + dz * dz + dw * dw;
#pragma unroll
    for (int o = 16; o; o >>= 1) ss += __shfl_xor_sync(0xffffffffu, ss, o);
    float r = rsqrtf(ss * (1.0f / 128.0f) + 1e-5f);
    float4 gv = ((const float4*)g)[lane], bv = ((const float4*)b)[lane];
    float4 o4 = make_float4(dx * r * gv.x + bv.x, dy * r * gv.y + bv.y,
                            dz * r * gv.z + bv.z, dw * r * gv.w + bv.w);
    ((float4*)(hout + (size_t)node * H))[lane] = o4;
}

// ---------------- K1b: node-level precompute of first-layer partials ----------------
__global__ __launch_bounds__(256, 2) void pre_kernel(
    const float* __restrict__ Wg1, const float* __restrict__ Wa1,
    const float* __restrict__ Wm1, int N)
{
    extern __shared__ float sm[];
    float* At = sm;                 // [64][132]
    float* Wt = At + 64 * 132;      // 2 x [32][128]

    int tx = threadIdx.x;
    int n_base = blockIdx.x * 64;
    { // gather h tile
        int le = tx >> 2, q = tx & 3;
        int n = n_base + le;
        bool valid = n < N;
        const float4* hr = (const float4*)(g_h + (size_t)(valid ? n : 0) * H);
        float* ar = At + le * 132;
        float4 z = make_float4(0.f, 0.f, 0.f, 0.f);
#pragma unroll
        for (int jj = 0; jj < 8; ++jj) { int j = q + jj * 4; *(float4*)(ar + j * 4) = valid ? hr[j] : z; }
    }
    // gemm's prologue __syncthreads covers At visibility

    int r0 = (tx >> 5) * 8;
    int c0 = (tx & 31) * 4;
    const float* Ws[5] = {Wg1, Wg1 + 128 * 128, Wa1, Wa1 + 128 * 128, Wm1};
    float* Os[5];
    Os[0] = g_Pgd; Os[1] = g_Pgs; Os[2] = g_Pad; Os[3] = g_Pas; Os[4] = g_Pms;

#pragma unroll 1
    for (int p = 0; p < 5; ++p) {
        float acc[8][4];
#pragma unroll
        for (int er = 0; er < 8; ++er)
#pragma unroll
            for (int cj = 0; cj < 4; ++cj) acc[er][cj] = 0.0f;
        gemm_acc_t<128, 132, 128>(At, Ws[p], 0, Wt, acc);
#pragma unroll
        for (int er = 0; er < 8; ++er) {
            int n = n_base + r0 + er;
            if (n < N) {
                *(float4*)(Os[p] + (size_t)n * H + c0) =
                    make_float4(acc[er][0], acc[er][1], acc[er][2], acc[er][3]);
            }
        }
    }
}

// ---------------- init: zero agg / denom / maxkey ----------------
__global__ __launch_bounds__(256) void init_kernel(int N)
{
    int i = blockIdx.x * 256 + threadIdx.x;
    if (i < N * H) g_agg[i] = 0.0f;
    if (i < N) { g_maxkey[i] = 0u; g_denom[i] = 0.0f; }
}

// ---------------- K2: per-edge MLPs (emb parts + second layers only) ----------------
__global__ __launch_bounds__(256, 2) void edge_kernel(
    const int* __restrict__ esrc, const int* __restrict__ edst,
    const float* __restrict__ emb,
    const float* __restrict__ Wm1, const float* __restrict__ bm1,
    const float* __restrict__ Wm2, const float* __restrict__ bm2,
    const float* __restrict__ Wa1, const float* __restrict__ ba1,
    const float* __restrict__ Wa2, const float* __restrict__ ba2,
    const float* __restrict__ Wg1, const float* __restrict__ bg1,
    const float* __restrict__ Wg2, const float* __restrict__ bg2,
    int E)
{
    extern __shared__ float sm[];
    float* Hm    = sm;                 // [64][132] hidden buffer
    float* Fe    = Hm + 64 * 132;      // [64][68]  edge_emb tile
    float* Wt    = Fe + 64 * 68;       // 2 x [32][128] weight tiles
    float* gateS = Wt + 2 * 32 * 128;  // [64]
    int*   sidx  = (int*)(gateS + 64); // [64]
    int*   didx  = sidx + 64;          // [64]

    int tx = threadIdx.x;
    int e_base = blockIdx.x * 64;

    if (tx < 64) {
        int e = e_base + tx;
        sidx[tx] = (e < E) ? esrc[e] : 0;
        didx[tx] = (e < E) ? edst[e] : 0;
    }
    { // gather edge_emb: 4 threads per edge, 4 float4 each
        int le = tx >> 2, q = tx & 3;
        int e = e_base + le;
        bool valid = e < E;
        const float4* em4 = (const float4*)(emb + (size_t)e * ED);
        float4 z = make_float4(0.f, 0.f, 0.f, 0.f);
        float* fr = Fe + le * 68;
#pragma unroll
        for (int jj = 0; jj < 4; ++jj) { int j = q + jj * 4; *(float4*)(fr + j * 4) = valid ? em4[j] : z; }
    }
    __syncthreads();

    int r0 = (tx >> 5) * 8;
    int c0 = (tx & 31) * 4;
    float acc[8][4];
    int srcs[8], dsts[8];
#pragma unroll
    for (int er = 0; er < 8; ++er) { srcs[er] = sidx[r0 + er]; dsts[er] = didx[r0 + er]; }

    // ---- gate path: gelu(Pgd[dst]+Pgs[src]+emb@Wg1_emb+bg1) @ Wg2 -> sigmoid
    load_acc_pp(acc, g_Pgd, g_Pgs, dsts, srcs, bg1, c0);
    gemm_acc_t<64, 68, 128>(Fe, Wg1 + (size_t)256 * 128, 0, Wt, acc);
    store_hidden_gelu(acc, Hm, 132, r0, c0);
    __syncthreads();
    { // 4 threads per row: 32 MACs each + quad shfl reduce
        int row = tx >> 2, q = tx & 3;
        const float* hr = Hm + row * 132 + q * 32;
        const float* w  = Wg2 + q * 32;
        float s = 0.f;
#pragma unroll 8
        for (int c = 0; c < 32; ++c) s = fmaf(hr[c], w[c], s);
        s += __shfl_xor_sync(0xffffffffu, s, 1);
        s += __shfl_xor_sync(0xffffffffu, s, 2);
        if (q == 0) gateS[row] = 1.0f / (1.0f + expf(-(s + bg2[0])));
    }
    // no extra sync needed: next gemm's prologue sync separates dot reads
    // of Hm from its later overwrite (writes occur after that gemm's trailing sync).

    // ---- attn path
    load_acc_pp(acc, g_Pad, g_Pas, dsts, srcs, ba1, c0);
    gemm_acc_t<64, 68, 128>(Fe, Wa1 + (size_t)256 * 128, 0, Wt, acc);
    store_hidden_gelu(acc, Hm, 132, r0, c0);
    __syncthreads();
    {
        int row = tx >> 2, q = tx & 3;
        const float* hr = Hm + row * 132 + q * 32;
        const float* w  = Wa2 + q * 32;
        float s = 0.f;
#pragma unroll 8
        for (int c = 0; c < 32; ++c) s = fmaf(hr[c], w[c], s);
        s += __shfl_xor_sync(0xffffffffu, s, 1);
        s += __shfl_xor_sync(0xffffffffu, s, 2);
        int e = e_base + row;
        if (q == 0 && e < E) g_score[e] = s + ba2[0];
    }

    // ---- msg path: gelu(Pms[src]+emb@Wm1_emb+bm1) @ Wm2 + bm2, then * gate
    load_acc_p(acc, g_Pms, srcs, bm1, c0);
    gemm_acc_t<64, 68, 128>(Fe, Wm1 + (size_t)128 * 128, 0, Wt, acc);
    store_hidden_gelu(acc, Hm, 132, r0, c0);
    init_acc_bias(acc, bm2 + c0);
    gemm_acc_t<128, 132, 128>(Hm, Wm2, 0, Wt, acc);
#pragma unroll
    for (int er = 0; er < 8; ++er) {
        int e = e_base + r0 + er;
        if (e < E) {
            float g = gateS[r0 + er];
            *(float4*)(g_msg + (size_t)e * H + c0) =
                make_float4(acc[er][0] * g, acc[er][1] * g, acc[er][2] * g, acc[er][3] * g);
        }
    }
}

// ---------------- K3: segment softmax ----------------
__global__ __launch_bounds__(256) void smax_kernel(const int* __restrict__ edst, int E)
{
    int e = blockIdx.x * 256 + threadIdx.x;
    if (e >= E) return;
    int i = __float_as_int(g_score[e]);
    unsigned key = (i >= 0) ? ((unsigned)i ^ 0x80000000u) : ~(unsigned)i;
    atomicMax(&g_maxkey[edst[e]], key);
}

__global__ __launch_bounds__(256) void exps_kernel(const int* __restrict__ edst, int E)
{
    int e = blockIdx.x * 256 + threadIdx.x;
    if (e >= E) return;
    int d = edst[e];
    unsigned k = g_maxkey[d];
    int bits = (k & 0x80000000u) ? (int)(k ^ 0x80000000u) : (int)~k;
    float m = __int_as_float(bits);
    float v = expf(g_score[e] - m);
    g_exp[e] = v;
    atomicAdd(&g_denom[d], v);
}

// ---------------- K4: edge_repr + scatter-add agg (vectorized red) ----------------
__global__ __launch_bounds__(256) void scatter_kernel(
    const int* __restrict__ edst, float* __restrict__ erep, int E)
{
    int idx = blockIdx.x * 256 + threadIdx.x;
    int e = idx >> 5;
    if (e >= E) return;
    int l4 = idx & 31;
    int d = edst[e];
    float w = g_exp[e] / fmaxf(g_denom[d], 1e-12f);
    float4 m = ((const float4*)(g_msg + (size_t)e * H))[l4];
    float4 r = make_float4(m.x * w, m.y * w, m.z * w, m.w * w);
    ((float4*)(erep + (size_t)e * H))[l4] = r;
    float* ag = g_agg + (size_t)d * H + (size_t)l4 * 4;
    asm volatile("red.global.add.v4.f32 [%0], {%1, %2, %3, %4};"
                 :: "l"(ag), "f"(r.x), "f"(r.y), "f"(r.z), "f"(r.w)
                 : "memory");
}

// ---------------- K5: node update + LN2 + FFN ----------------
__global__ __launch_bounds__(256, 1) void node_kernel(
    const float* __restrict__ x,
    const float* __restrict__ Wself, const float* __restrict__ bself,
    const float* __restrict__ Wagg, const float* __restrict__ bagg,
    const float* __restrict__ g2, const float* __restrict__ b2,
    const float* __restrict__ Wf1, const float* __restrict__ bf1,
    const float* __restrict__ Wf2, const float* __restrict__ bf2,
    float* __restrict__ out, int N)
{
    extern __shared__ float sm[];
    float* At   = sm;                  // [64][132] A operand
    float* Ot   = At + 64 * 132;       // [64][132] out1 (pre-LN residual)
    float* H2   = Ot + 64 * 132;       // [64][260] FFN hidden
    float* Wt   = H2 + 64 * 260;       // 2 x [32][128]
    float* mu   = Wt + 2 * 32 * 128;   // [64]
    float* rstd = mu + 64;             // [64]

    int tx = threadIdx.x;
    int n_base = blockIdx.x * 64;
    int r0 = (tx >> 5) * 8;
    int c0 = (tx & 31) * 4;
    float acc[8][4];

    { // gather h
        int le = tx >> 2, q = tx & 3;
        int n = n_base + le;
        bool valid = n < N;
        const float4* hr = (const float4*)(g_h + (size_t)(valid ? n : 0) * H);
        float* ar = At + le * 132;
        float4 z = make_float4(0.f, 0.f, 0.f, 0.f);
#pragma unroll
        for (int jj = 0; jj < 8; ++jj) { int j = q + jj * 4; *(float4*)(ar + j * 4) = valid ? hr[j] : z; }
    }

    { // acc = bself + bagg
        float4 a0 = *(const float4*)(bself + c0);
        float4 g0 = *(const float4*)(bagg + c0);
        float4 bv = make_float4(a0.x + g0.x, a0.y + g0.y, a0.z + g0.z, a0.w + g0.w);
#pragma unroll
        for (int er = 0; er < 8; ++er) {
            acc[er][0] = bv.x; acc[er][1] = bv.y; acc[er][2] = bv.z; acc[er][3] = bv.w;
        }
    }
    gemm_acc_t<128, 132, 128>(At, Wself, 0, Wt, acc);

    { // overwrite At with agg (gemm's trailing sync makes this safe)
        int le = tx >> 2, q = tx & 3;
        int n = n_base + le;
        bool valid = n < N;
        const float4* gr = (const float4*)(g_agg + (size_t)(valid ? n : 0) * H);
        float* ar = At + le * 132;
        float4 z = make_float4(0.f, 0.f, 0.f, 0.f);
#pragma unroll
        for (int jj = 0; jj < 8; ++jj) { int j = q + jj * 4; *(float4*)(ar + j * 4) = valid ? gr[j] : z; }
    }
    gemm_acc_t<128, 132, 128>(At, Wagg, 0, Wt, acc);

    // out1 = x + update -> Ot
#pragma unroll
    for (int er = 0; er < 8; ++er) {
        int n = n_base + r0 + er;
        float4 x0 = make_float4(0.f, 0.f, 0.f, 0.f);
        if (n < N) x0 = *(const float4*)(x + (size_t)n * H + c0);
        *(float4*)(Ot + (r0 + er) * 132 + c0) =
            make_float4(acc[er][0] + x0.x, acc[er][1] + x0.y,
                        acc[er][2] + x0.z, acc[er][3] + x0.w);
    }
    __syncthreads();

    // LN2 stats: 4 threads per row, single pass
    {
        int row = tx >> 2, q = tx & 3;
        const float* orow = Ot + row * 132 + q * 32;
        float s = 0.f, s2 = 0.f;
#pragma unroll 8
        for (int c = 0; c < 32; ++c) { float v = orow[c]; s += v; s2 = fmaf(v, v, s2); }
        s  += __shfl_xor_sync(0xffffffffu, s, 1);
        s  += __shfl_xor_sync(0xffffffffu, s, 2);
        s2 += __shfl_xor_sync(0xffffffffu, s2, 1);
        s2 += __shfl_xor_sync(0xffffffffu, s2, 2);
        if (q == 0) {
            float m = s * (1.0f / 128.0f);
            mu[row] = m;
            rstd[row] = rsqrtf(fmaxf(s2 * (1.0f / 128.0f) - m * m, 0.0f) + 1e-5f);
        }
    }
    __syncthreads();

    { // normalize -> At
        int le = tx & 63, cb = tx >> 6;
        float m = mu[le], r = rstd[le];
        const float* orow = Ot + le * 132;
        float* ar = At + le * 132;
#pragma unroll 4
        for (int c = cb * 32; c < cb * 32 + 32; ++c)
            ar[c] = (orow[c] - m) * r * g2[c] + b2[c];
    }

    // FFN layer 1: [64][128] @ [128][256] in two 128-col chunks
#pragma unroll 1
    for (int chunk = 0; chunk < 2; ++chunk) {
        int coff = chunk * 128;
        init_acc_bias(acc, bf1 + coff + c0);
        gemm_acc_t<128, 132, 256>(At, Wf1, coff, Wt, acc);
        store_hidden_gelu(acc, H2 + coff, 260, r0, c0);
    }

    // FFN layer 2: [64][256] @ [256][128], + residual -> out
    init_acc_bias(acc, bf2 + c0);
    gemm_acc_t<256, 260, 128>(H2, Wf2, 0, Wt, acc);
#pragma unroll
    for (int er = 0; er < 8; ++er) {
        int n = n_base + r0 + er;
        if (n < N) {
            const float* orow = Ot + (r0 + er) * 132 + c0;
            *(float4*)(out + (size_t)n * H + c0) =
                make_float4(orow[0] + acc[er][0], orow[1] + acc[er][1],
                            orow[2] + acc[er][2], orow[3] + acc[er][3]);
        }
    }
}

// ---------------- launch ----------------
extern "C" void kernel_launch(void* const* d_in, const int* in_sizes, int n_in,
                              void* d_out, int out_size)
{
    const float* x     = (const float*)d_in[0];
    const int*   esrc  = (const int*)d_in[1];
    const int*   edst  = (const int*)d_in[2];
    const float* emb   = (const float*)d_in[3];
    const float* ln1g  = (const float*)d_in[4];
    const float* ln1b  = (const float*)d_in[5];
    const float* ln2g  = (const float*)d_in[6];
    const float* ln2b  = (const float*)d_in[7];
    const float* Wself = (const float*)d_in[8];
    const float* bself = (const float*)d_in[9];
    const float* Wm1   = (const float*)d_in[10];
    const float* bm1   = (const float*)d_in[11];
    const float* Wm2   = (const float*)d_in[12];
    const float* bm2   = (const float*)d_in[13];
    const float* Wa1   = (const float*)d_in[14];
    const float* ba1   = (const float*)d_in[15];
    const float* Wa2   = (const float*)d_in[16];
    const float* ba2   = (const float*)d_in[17];
    const float* Wg1   = (const float*)d_in[18];
    const float* bg1   = (const float*)d_in[19];
    const float* Wg2   = (const float*)d_in[20];
    const float* bg2   = (const float*)d_in[21];
    const float* Wagg  = (const float*)d_in[22];
    const float* bagg  = (const float*)d_in[23];
    const float* Wf1   = (const float*)d_in[24];
    const float* bf1   = (const float*)d_in[25];
    const float* Wf2   = (const float*)d_in[26];
    const float* bf2   = (const float*)d_in[27];

    int N = in_sizes[0] / H;
    int E = in_sizes[1];

    float* out_nodes = (float*)d_out;
    float* out_edges = out_nodes + (size_t)N * H;

    const int PRE_SMEM  = (64 * 132 + 2 * 32 * 128) * 4;                          // 66560
    const int EDGE_SMEM = (64 * 132 + 64 * 68 + 2 * 32 * 128 + 64 + 128) * 4;     // 84736
    const int NODE_SMEM = (64 * 132 * 2 + 64 * 260 + 2 * 32 * 128 + 128) * 4;     // 167424
    cudaFuncSetAttribute(pre_kernel,  cudaFuncAttributeMaxDynamicSharedMemorySize, PRE_SMEM);
    cudaFuncSetAttribute(edge_kernel, cudaFuncAttributeMaxDynamicSharedMemorySize, EDGE_SMEM);
    cudaFuncSetAttribute(node_kernel, cudaFuncAttributeMaxDynamicSharedMemorySize, NODE_SMEM);

    float* hbuf;
    cudaGetSymbolAddress((void**)&hbuf, g_h);

    ln1_kernel<<<(N + 7) / 8, 256>>>(x, ln1g, ln1b, hbuf, N);
    pre_kernel<<<(N + 63) / 64, 256, PRE_SMEM>>>(Wg1, Wa1, Wm1, N);
    init_kernel<<<(N * H + 255) / 256, 256>>>(N);
    edge_kernel<<<(E + 63) / 64, 256, EDGE_SMEM>>>(
        esrc, edst, emb, Wm1, bm1, Wm2, bm2, Wa1, ba1, Wa2, ba2,
        Wg1, bg1, Wg2, bg2, E);
    smax_kernel<<<(E + 255) / 256, 256>>>(edst, E);
    exps_kernel<<<(E + 255) / 256, 256>>>(edst, E);
    scatter_kernel<<<((size_t)E * 32 + 255) / 256, 256>>>(edst, out_edges, E);
    node_kernel<<<(N + 63) / 64, 256, NODE_SMEM>>>(
        x, Wself, bself, Wagg, bagg, ln2g, ln2b, Wf1, bf1, Wf2, bf2,
        out_nodes, N);
}

// round 13
// speedup vs baseline: 4.3076x; 1.0327x over previous
#include <cuda_runtime.h>
#include <math.h>

#define H   128
#define ED  64
#define MAXN 100000
#define MAXE 500000

// ---------------- scratch (device globals; no allocations allowed) ----------------
__device__ float    g_h[(size_t)MAXN * H];      // LN1 output; later reused to park out1
__device__ float    g_msg[(size_t)MAXE * H];    // gated messages
__device__ float    g_score[MAXE];              // attention scores
__device__ float    g_exp[MAXE];                // exp(score - max)
__device__ unsigned g_maxkey[MAXN];             // ordered-uint segment max
__device__ float    g_denom[MAXN];              // segment sum of exp
__device__ float    g_agg[(size_t)MAXN * H];    // aggregated messages
// node-level precomputed first-layer partials (no bias)
__device__ float    g_Pgd[(size_t)MAXN * H];    // h @ Wg1[0:128]    (dst part, gate)
__device__ float    g_Pgs[(size_t)MAXN * H];    // h @ Wg1[128:256]  (src part, gate)
__device__ float    g_Pad[(size_t)MAXN * H];    // h @ Wa1[0:128]    (dst part, attn)
__device__ float    g_Pas[(size_t)MAXN * H];    // h @ Wa1[128:256]  (src part, attn)
__device__ float    g_Pms[(size_t)MAXN * H];    // h @ Wm1[0:128]    (src part, msg)

// ---------------- helpers ----------------
__device__ __forceinline__ float gelu_exact(float v) {
    return 0.5f * v * (1.0f + erff(v * 0.70710678118654752440f));
}

__device__ __forceinline__ void cp16(float* dst, const float* src) {
    unsigned s = (unsigned)__cvta_generic_to_shared(dst);
    asm volatile("cp.async.cg.shared.global [%0], [%1], 16;" :: "r"(s), "l"(src) : "memory");
}
#define CP_COMMIT() asm volatile("cp.async.commit_group;" ::: "memory")
#define CP_WAIT0()  asm volatile("cp.async.wait_group 0;" ::: "memory")

// ---------------- templated tiled GEMM with cp.async double-buffered weights ----
// C[64 rows][128 cols] += A[64][K] * W[K][128]; A in smem (row stride LDA),
// W streamed global->smem via cp.async into Wts (2 buffers of 32x128).
// 256 threads = 8 warps. Warp w: rows w*8..w*8+7. Lane l: cols l*4..l*4+3.
template<int K, int LDA, int LDW>
__device__ __forceinline__ void gemm_acc_t(
    const float* __restrict__ As,
    const float* __restrict__ Wg, int woff,
    float* __restrict__ Wts, float acc[8][4])
{
    constexpr int NT = K / 32;
    const int tx  = threadIdx.x;
    const int wid = tx >> 5;
    const int c0  = (tx & 31) * 4;
    const float* abase = As + (wid * 8) * LDA;
    const float* wptr  = Wg + (size_t)wid * LDW + woff + c0;   // row wid of tile
    float* s0 = Wts + wid * 128 + c0;                          // buf0 store slot

    // prologue: tile 0 -> buf0
#pragma unroll
    for (int i = 0; i < 4; ++i)
        cp16(s0 + i * 8 * 128, wptr + (size_t)(i * 8) * LDW);
    CP_COMMIT();
    CP_WAIT0();
    __syncthreads();      // tile0 visible; also orders caller's As writes

    int cur = 0;
#pragma unroll 1
    for (int t = 0; t < NT; ++t) {
        if (t + 1 < NT) {   // issue next tile into the other buffer
            float* sn = s0 + (cur ? 0 : 4096);
            const float* wn = wptr + (size_t)((t + 1) * 32) * LDW;
#pragma unroll
            for (int i = 0; i < 4; ++i)
                cp16(sn + i * 8 * 128, wn + (size_t)(i * 8) * LDW);
            CP_COMMIT();
        }
        const float* wb = Wts + (cur ? 4096 : 0);
        const float* ab = abase + t * 32;
#pragma unroll
        for (int kk4 = 0; kk4 < 32; kk4 += 4) {
            float4 b0 = *(const float4*)(wb + (kk4 + 0) * 128 + c0);
            float4 b1 = *(const float4*)(wb + (kk4 + 1) * 128 + c0);
            float4 b2 = *(const float4*)(wb + (kk4 + 2) * 128 + c0);
            float4 b3 = *(const float4*)(wb + (kk4 + 3) * 128 + c0);
#pragma unroll
            for (int er = 0; er < 8; ++er) {
                float4 a = *(const float4*)(ab + er * LDA + kk4);
                acc[er][0] = fmaf(a.x, b0.x, acc[er][0]);
                acc[er][1] = fmaf(a.x, b0.y, acc[er][1]);
                acc[er][2] = fmaf(a.x, b0.z, acc[er][2]);
                acc[er][3] = fmaf(a.x, b0.w, acc[er][3]);
                acc[er][0] = fmaf(a.y, b1.x, acc[er][0]);
                acc[er][1] = fmaf(a.y, b1.y, acc[er][1]);
                acc[er][2] = fmaf(a.y, b1.z, acc[er][2]);
                acc[er][3] = fmaf(a.y, b1.w, acc[er][3]);
                acc[er][0] = fmaf(a.z, b2.x, acc[er][0]);
                acc[er][1] = fmaf(a.z, b2.y, acc[er][1]);
                acc[er][2] = fmaf(a.z, b2.z, acc[er][2]);
                acc[er][3] = fmaf(a.z, b2.w, acc[er][3]);
                acc[er][0] = fmaf(a.w, b3.x, acc[er][0]);
                acc[er][1] = fmaf(a.w, b3.y, acc[er][1]);
                acc[er][2] = fmaf(a.w, b3.z, acc[er][2]);
                acc[er][3] = fmaf(a.w, b3.w, acc[er][3]);
            }
        }
        if (t + 1 < NT) {
            CP_WAIT0();
            __syncthreads();
            cur ^= 1;
        }
    }
    __syncthreads();   // protect Wts and As for the caller's next phase
}

// b4 must already point at this thread's 4 columns (base + c0)
__device__ __forceinline__ void init_acc_bias(float acc[8][4], const float* __restrict__ b4) {
    float4 bv = *(const float4*)b4;
#pragma unroll
    for (int er = 0; er < 8; ++er) {
        acc[er][0] = bv.x; acc[er][1] = bv.y; acc[er][2] = bv.z; acc[er][3] = bv.w;
    }
}

// acc = Pd[dst] + Ps[src] + bias  (per-thread float4 cells, from global/L2)
__device__ __forceinline__ void load_acc_pp(
    float acc[8][4], const float* __restrict__ Pd, const float* __restrict__ Ps,
    const int* dsts, const int* srcs, const float* __restrict__ b, int c0)
{
    float4 bv = *(const float4*)(b + c0);
#pragma unroll
    for (int er = 0; er < 8; ++er) {
        float4 d0 = *(const float4*)(Pd + (size_t)dsts[er] * H + c0);
        float4 s0 = *(const float4*)(Ps + (size_t)srcs[er] * H + c0);
        acc[er][0] = d0.x + s0.x + bv.x;
        acc[er][1] = d0.y + s0.y + bv.y;
        acc[er][2] = d0.z + s0.z + bv.z;
        acc[er][3] = d0.w + s0.w + bv.w;
    }
}

// acc = Ps[src] + bias
__device__ __forceinline__ void load_acc_p(
    float acc[8][4], const float* __restrict__ Ps,
    const int* srcs, const float* __restrict__ b, int c0)
{
    float4 bv = *(const float4*)(b + c0);
#pragma unroll
    for (int er = 0; er < 8; ++er) {
        float4 s0 = *(const float4*)(Ps + (size_t)srcs[er] * H + c0);
        acc[er][0] = s0.x + bv.x;
        acc[er][1] = s0.y + bv.y;
        acc[er][2] = s0.z + bv.z;
        acc[er][3] = s0.w + bv.w;
    }
}

__device__ __forceinline__ void store_hidden_gelu(float acc[8][4], float* __restrict__ Hm,
                                                  int stride, int r0, int c0) {
#pragma unroll
    for (int er = 0; er < 8; ++er) {
        float4 v = make_float4(gelu_exact(acc[er][0]), gelu_exact(acc[er][1]),
                               gelu_exact(acc[er][2]), gelu_exact(acc[er][3]));
        *(float4*)(Hm + (r0 + er) * stride + c0) = v;
    }
}

// ---------------- K1: LN1 fused + node-level precompute of first-layer partials ----
__global__ __launch_bounds__(256, 2) void pre_kernel(
    const float* __restrict__ x,
    const float* __restrict__ ln1g, const float* __restrict__ ln1b,
    const float* __restrict__ Wg1, const float* __restrict__ Wa1,
    const float* __restrict__ Wm1, int N)
{
    extern __shared__ float sm[];
    float* At = sm;                 // [64][132]
    float* Wt = At + 64 * 132;      // 2 x [32][128]
    float* mu = Wt + 2 * 32 * 128;  // [64]
    float* rs = mu + 64;            // [64]

    int tx = threadIdx.x;
    int n_base = blockIdx.x * 64;
    { // gather x tile
        int le = tx >> 2, q = tx & 3;
        int n = n_base + le;
        bool valid = n < N;
        const float4* xr = (const float4*)(x + (size_t)(valid ? n : 0) * H);
        float* ar = At + le * 132;
        float4 z = make_float4(0.f, 0.f, 0.f, 0.f);
#pragma unroll
        for (int jj = 0; jj < 8; ++jj) { int j = q + jj * 4; *(float4*)(ar + j * 4) = valid ? xr[j] : z; }
    }
    __syncthreads();

    { // LN1 stats: 4 threads per row
        int row = tx >> 2, q = tx & 3;
        const float* xr = At + row * 132 + q * 32;
        float s = 0.f, s2 = 0.f;
#pragma unroll 8
        for (int c = 0; c < 32; ++c) { float v = xr[c]; s += v; s2 = fmaf(v, v, s2); }
        s  += __shfl_xor_sync(0xffffffffu, s, 1);
        s  += __shfl_xor_sync(0xffffffffu, s, 2);
        s2 += __shfl_xor_sync(0xffffffffu, s2, 1);
        s2 += __shfl_xor_sync(0xffffffffu, s2, 2);
        if (q == 0) {
            float m = s * (1.0f / 128.0f);
            mu[row] = m;
            rs[row] = rsqrtf(fmaxf(s2 * (1.0f / 128.0f) - m * m, 0.0f) + 1e-5f);
        }
    }
    __syncthreads();

    { // normalize At in place + write g_h (coalesced float4)
#pragma unroll
        for (int i = 0; i < 8; ++i) {
            int f4 = tx + i * 256;          // 2048 float4 = 64x128
            int row = f4 >> 5;
            int c4 = (f4 & 31);
            float m = mu[row], r = rs[row];
            float4 v = *(const float4*)(At + row * 132 + c4 * 4);
            float4 g = ((const float4*)ln1g)[c4];
            float4 b = ((const float4*)ln1b)[c4];
            float4 nv = make_float4((v.x - m) * r * g.x + b.x, (v.y - m) * r * g.y + b.y,
                                    (v.z - m) * r * g.z + b.z, (v.w - m) * r * g.w + b.w);
            *(float4*)(At + row * 132 + c4 * 4) = nv;
            int n = n_base + row;
            if (n < N) ((float4*)(g_h + (size_t)n * H))[c4] = nv;
        }
    }
    // gemm's prologue __syncthreads orders the At writes

    int r0 = (tx >> 5) * 8;
    int c0 = (tx & 31) * 4;
    const float* Ws[5] = {Wg1, Wg1 + 128 * 128, Wa1, Wa1 + 128 * 128, Wm1};
    float* Os[5];
    Os[0] = g_Pgd; Os[1] = g_Pgs; Os[2] = g_Pad; Os[3] = g_Pas; Os[4] = g_Pms;

#pragma unroll 1
    for (int p = 0; p < 5; ++p) {
        float acc[8][4];
#pragma unroll
        for (int er = 0; er < 8; ++er)
#pragma unroll
            for (int cj = 0; cj < 4; ++cj) acc[er][cj] = 0.0f;
        gemm_acc_t<128, 132, 128>(At, Ws[p], 0, Wt, acc);
#pragma unroll
        for (int er = 0; er < 8; ++er) {
            int n = n_base + r0 + er;
            if (n < N) {
                *(float4*)(Os[p] + (size_t)n * H + c0) =
                    make_float4(acc[er][0], acc[er][1], acc[er][2], acc[er][3]);
            }
        }
    }
}

// ---------------- init: zero agg / denom / maxkey ----------------
__global__ __launch_bounds__(256) void init_kernel(int N)
{
    int i = blockIdx.x * 256 + threadIdx.x;
    if (i < N * H) g_agg[i] = 0.0f;
    if (i < N) { g_maxkey[i] = 0u; g_denom[i] = 0.0f; }
}

// ---------------- K2: per-edge MLPs (emb parts + second layers only) ----------------
__global__ __launch_bounds__(256, 2) void edge_kernel(
    const int* __restrict__ esrc, const int* __restrict__ edst,
    const float* __restrict__ emb,
    const float* __restrict__ Wm1, const float* __restrict__ bm1,
    const float* __restrict__ Wm2, const float* __restrict__ bm2,
    const float* __restrict__ Wa1, const float* __restrict__ ba1,
    const float* __restrict__ Wa2, const float* __restrict__ ba2,
    const float* __restrict__ Wg1, const float* __restrict__ bg1,
    const float* __restrict__ Wg2, const float* __restrict__ bg2,
    int E)
{
    extern __shared__ float sm[];
    float* Hm    = sm;                 // [64][132] hidden buffer
    float* Fe    = Hm + 64 * 132;      // [64][68]  edge_emb tile
    float* Wt    = Fe + 64 * 68;       // 2 x [32][128] weight tiles
    float* gateS = Wt + 2 * 32 * 128;  // [64]
    int*   sidx  = (int*)(gateS + 64); // [64]
    int*   didx  = sidx + 64;          // [64]

    int tx = threadIdx.x;
    int e_base = blockIdx.x * 64;

    if (tx < 64) {
        int e = e_base + tx;
        sidx[tx] = (e < E) ? esrc[e] : 0;
        didx[tx] = (e < E) ? edst[e] : 0;
    }
    { // gather edge_emb: 4 threads per edge, 4 float4 each
        int le = tx >> 2, q = tx & 3;
        int e = e_base + le;
        bool valid = e < E;
        const float4* em4 = (const float4*)(emb + (size_t)e * ED);
        float4 z = make_float4(0.f, 0.f, 0.f, 0.f);
        float* fr = Fe + le * 68;
#pragma unroll
        for (int jj = 0; jj < 4; ++jj) { int j = q + jj * 4; *(float4*)(fr + j * 4) = valid ? em4[j] : z; }
    }
    __syncthreads();

    int r0 = (tx >> 5) * 8;
    int c0 = (tx & 31) * 4;
    float acc[8][4];
    int srcs[8], dsts[8];
#pragma unroll
    for (int er = 0; er < 8; ++er) { srcs[er] = sidx[r0 + er]; dsts[er] = didx[r0 + er]; }

    // ---- gate path: gelu(Pgd[dst]+Pgs[src]+emb@Wg1_emb+bg1) @ Wg2 -> sigmoid
    load_acc_pp(acc, g_Pgd, g_Pgs, dsts, srcs, bg1, c0);
    gemm_acc_t<64, 68, 128>(Fe, Wg1 + (size_t)256 * 128, 0, Wt, acc);
    store_hidden_gelu(acc, Hm, 132, r0, c0);
    __syncthreads();
    { // 4 threads per row: 32 MACs each + quad shfl reduce
        int row = tx >> 2, q = tx & 3;
        const float* hr = Hm + row * 132 + q * 32;
        const float* w  = Wg2 + q * 32;
        float s = 0.f;
#pragma unroll 8
        for (int c = 0; c < 32; ++c) s = fmaf(hr[c], w[c], s);
        s += __shfl_xor_sync(0xffffffffu, s, 1);
        s += __shfl_xor_sync(0xffffffffu, s, 2);
        if (q == 0) gateS[row] = 1.0f / (1.0f + expf(-(s + bg2[0])));
    }
    // next gemm's prologue sync separates dot reads of Hm from its overwrite

    // ---- attn path
    load_acc_pp(acc, g_Pad, g_Pas, dsts, srcs, ba1, c0);
    gemm_acc_t<64, 68, 128>(Fe, Wa1 + (size_t)256 * 128, 0, Wt, acc);
    store_hidden_gelu(acc, Hm, 132, r0, c0);
    __syncthreads();
    {
        int row = tx >> 2, q = tx & 3;
        const float* hr = Hm + row * 132 + q * 32;
        const float* w  = Wa2 + q * 32;
        float s = 0.f;
#pragma unroll 8
        for (int c = 0; c < 32; ++c) s = fmaf(hr[c], w[c], s);
        s += __shfl_xor_sync(0xffffffffu, s, 1);
        s += __shfl_xor_sync(0xffffffffu, s, 2);
        int e = e_base + row;
        if (q == 0 && e < E) g_score[e] = s + ba2[0];
    }

    // ---- msg path: gelu(Pms[src]+emb@Wm1_emb+bm1) @ Wm2 + bm2, then * gate
    load_acc_p(acc, g_Pms, srcs, bm1, c0);
    gemm_acc_t<64, 68, 128>(Fe, Wm1 + (size_t)128 * 128, 0, Wt, acc);
    store_hidden_gelu(acc, Hm, 132, r0, c0);
    init_acc_bias(acc, bm2 + c0);
    gemm_acc_t<128, 132, 128>(Hm, Wm2, 0, Wt, acc);
#pragma unroll
    for (int er = 0; er < 8; ++er) {
        int e = e_base + r0 + er;
        if (e < E) {
            float g = gateS[r0 + er];
            *(float4*)(g_msg + (size_t)e * H + c0) =
                make_float4(acc[er][0] * g, acc[er][1] * g, acc[er][2] * g, acc[er][3] * g);
        }
    }
}

// ---------------- K3: segment softmax ----------------
__global__ __launch_bounds__(256) void smax_kernel(const int* __restrict__ edst, int E)
{
    int e = blockIdx.x * 256 + threadIdx.x;
    if (e >= E) return;
    int i = __float_as_int(g_score[e]);
    unsigned key = (i >= 0) ? ((unsigned)i ^ 0x80000000u) : ~(unsigned)i;
    atomicMax(&g_maxkey[edst[e]], key);
}

__global__ __launch_bounds__(256) void exps_kernel(const int* __restrict__ edst, int E)
{
    int e = blockIdx.x * 256 + threadIdx.x;
    if (e >= E) return;
    int d = edst[e];
    unsigned k = g_maxkey[d];
    int bits = (k & 0x80000000u) ? (int)(k ^ 0x80000000u) : (int)~k;
    float m = __int_as_float(bits);
    float v = expf(g_score[e] - m);
    g_exp[e] = v;
    atomicAdd(&g_denom[d], v);
}

// ---------------- K4: edge_repr + scatter-add agg (vectorized red) ----------------
__global__ __launch_bounds__(256) void scatter_kernel(
    const int* __restrict__ edst, float* __restrict__ erep, int E)
{
    int idx = blockIdx.x * 256 + threadIdx.x;
    int e = idx >> 5;
    if (e >= E) return;
    int l4 = idx & 31;
    int d = edst[e];
    float w = g_exp[e] / fmaxf(g_denom[d], 1e-12f);
    float4 m = ((const float4*)(g_msg + (size_t)e * H))[l4];
    float4 r = make_float4(m.x * w, m.y * w, m.z * w, m.w * w);
    ((float4*)(erep + (size_t)e * H))[l4] = r;
    float* ag = g_agg + (size_t)d * H + (size_t)l4 * 4;
    asm volatile("red.global.add.v4.f32 [%0], {%1, %2, %3, %4};"
                 :: "l"(ag), "f"(r.x), "f"(r.y), "f"(r.z), "f"(r.w)
                 : "memory");
}

// ---------------- K5: node update + LN2 + FFN (2 blocks/SM) ----------------
__global__ __launch_bounds__(256, 2) void node_kernel(
    const float* __restrict__ x,
    const float* __restrict__ Wself, const float* __restrict__ bself,
    const float* __restrict__ Wagg, const float* __restrict__ bagg,
    const float* __restrict__ g2, const float* __restrict__ b2,
    const float* __restrict__ Wf1, const float* __restrict__ bf1,
    const float* __restrict__ Wf2, const float* __restrict__ bf2,
    float* __restrict__ out, int N)
{
    extern __shared__ float sm[];
    float* At = sm;                  // [64][132] A operand (h, then agg, then LN2(out1))
    float* Hc = At + 64 * 132;       // [64][132] FFN hidden chunk
    float* Wt = Hc + 64 * 132;       // 2 x [32][128]

    int tx = threadIdx.x;
    int n_base = blockIdx.x * 64;
    int r0 = (tx >> 5) * 8;
    int c0 = (tx & 31) * 4;
    float acc[8][4];

    { // gather h
        int le = tx >> 2, q = tx & 3;
        int n = n_base + le;
        bool valid = n < N;
        const float4* hr = (const float4*)(g_h + (size_t)(valid ? n : 0) * H);
        float* ar = At + le * 132;
        float4 z = make_float4(0.f, 0.f, 0.f, 0.f);
#pragma unroll
        for (int jj = 0; jj < 8; ++jj) { int j = q + jj * 4; *(float4*)(ar + j * 4) = valid ? hr[j] : z; }
    }

    { // acc = bself + bagg
        float4 a0 = *(const float4*)(bself + c0);
        float4 g0 = *(const float4*)(bagg + c0);
#pragma unroll
        for (int er = 0; er < 8; ++er) {
            acc[er][0] = a0.x + g0.x; acc[er][1] = a0.y + g0.y;
            acc[er][2] = a0.z + g0.z; acc[er][3] = a0.w + g0.w;
        }
    }
    gemm_acc_t<128, 132, 128>(At, Wself, 0, Wt, acc);

    { // overwrite At with agg (gemm's trailing sync makes this safe)
        int le = tx >> 2, q = tx & 3;
        int n = n_base + le;
        bool valid = n < N;
        const float4* gr = (const float4*)(g_agg + (size_t)(valid ? n : 0) * H);
        float* ar = At + le * 132;
        float4 z = make_float4(0.f, 0.f, 0.f, 0.f);
#pragma unroll
        for (int jj = 0; jj < 8; ++jj) { int j = q + jj * 4; *(float4*)(ar + j * 4) = valid ? gr[j] : z; }
    }
    gemm_acc_t<128, 132, 128>(At, Wagg, 0, Wt, acc);

    // out1 = x + update: park in g_h rows (ours alone), LN2 stats per warp-row
    // (warp holds a full 128-col row across its 32 lanes), normalized -> At.
    float4 gq = *(const float4*)(g2 + c0);
    float4 bq = *(const float4*)(b2 + c0);
#pragma unroll
    for (int er = 0; er < 8; ++er) {
        int n = n_base + r0 + er;
        float4 x0 = make_float4(0.f, 0.f, 0.f, 0.f);
        if (n < N) x0 = *(const float4*)(x + (size_t)n * H + c0);
        float o0 = acc[er][0] + x0.x, o1 = acc[er][1] + x0.y;
        float o2 = acc[er][2] + x0.z, o3 = acc[er][3] + x0.w;
        if (n < N)
            *(float4*)(g_h + (size_t)n * H + c0) = make_float4(o0, o1, o2, o3);
        float s  = o0 + o1 + o2 + o3;
        float s2 = o0 * o0 + o1 * o1 + o2 * o2 + o3 * o3;
#pragma unroll
        for (int o = 16; o; o >>= 1) {
            s  += __shfl_xor_sync(0xffffffffu, s,  o);
            s2 += __shfl_xor_sync(0xffffffffu, s2, o);
        }
        float m = s * (1.0f / 128.0f);
        float r = rsqrtf(fmaxf(s2 * (1.0f / 128.0f) - m * m, 0.0f) + 1e-5f);
        *(float4*)(At + (r0 + er) * 132 + c0) =
            make_float4((o0 - m) * r * gq.x + bq.x, (o1 - m) * r * gq.y + bq.y,
                        (o2 - m) * r * gq.z + bq.z, (o3 - m) * r * gq.w + bq.w);
    }
    // gemm prologue sync orders the At writes

    // FFN chunked: for each 128-col chunk of Wf1, compute gelu hidden -> Hc,
    // then accumulate FFN2 partial (Wf2 row-block) into persistent accB.
    float accB[8][4];
    {
        float4 bv = *(const float4*)(bf2 + c0);
#pragma unroll
        for (int er = 0; er < 8; ++er) {
            accB[er][0] = bv.x; accB[er][1] = bv.y; accB[er][2] = bv.z; accB[er][3] = bv.w;
        }
    }
#pragma unroll 1
    for (int chunk = 0; chunk < 2; ++chunk) {
        int coff = chunk * 128;
        init_acc_bias(acc, bf1 + coff + c0);
        gemm_acc_t<128, 132, 256>(At, Wf1, coff, Wt, acc);
        store_hidden_gelu(acc, Hc, 132, r0, c0);
        gemm_acc_t<128, 132, 128>(Hc, Wf2 + (size_t)coff * 128, 0, Wt, accB);
    }

    // final: out = out1(g_h) + accB
#pragma unroll
    for (int er = 0; er < 8; ++er) {
        int n = n_base + r0 + er;
        if (n < N) {
            float4 o = *(const float4*)(g_h + (size_t)n * H + c0);
            *(float4*)(out + (size_t)n * H + c0) =
                make_float4(o.x + accB[er][0], o.y + accB[er][1],
                            o.z + accB[er][2], o.w + accB[er][3]);
        }
    }
}

// ---------------- launch ----------------
extern "C" void kernel_launch(void* const* d_in, const int* in_sizes, int n_in,
                              void* d_out, int out_size)
{
    const float* x     = (const float*)d_in[0];
    const int*   esrc  = (const int*)d_in[1];
    const int*   edst  = (const int*)d_in[2];
    const float* emb   = (const float*)d_in[3];
    const float* ln1g  = (const float*)d_in[4];
    const float* ln1b  = (const float*)d_in[5];
    const float* ln2g  = (const float*)d_in[6];
    const float* ln2b  = (const float*)d_in[7];
    const float* Wself = (const float*)d_in[8];
    const float* bself = (const float*)d_in[9];
    const float* Wm1   = (const float*)d_in[10];
    const float* bm1   = (const float*)d_in[11];
    const float* Wm2   = (const float*)d_in[12];
    const float* bm2   = (const float*)d_in[13];
    const float* Wa1   = (const float*)d_in[14];
    const float* ba1   = (const float*)d_in[15];
    const float* Wa2   = (const float*)d_in[16];
    const float* ba2   = (const float*)d_in[17];
    const float* Wg1   = (const float*)d_in[18];
    const float* bg1   = (const float*)d_in[19];
    const float* Wg2   = (const float*)d_in[20];
    const float* bg2   = (const float*)d_in[21];
    const float* Wagg  = (const float*)d_in[22];
    const float* bagg  = (const float*)d_in[23];
    const float* Wf1   = (const float*)d_in[24];
    const float* bf1   = (const float*)d_in[25];
    const float* Wf2   = (const float*)d_in[26];
    const float* bf2   = (const float*)d_in[27];

    int N = in_sizes[0] / H;
    int E = in_sizes[1];

    float* out_nodes = (float*)d_out;
    float* out_edges = out_nodes + (size_t)N * H;

    const int PRE_SMEM  = (64 * 132 + 2 * 32 * 128 + 128) * 4;                    // 67072
    const int EDGE_SMEM = (64 * 132 + 64 * 68 + 2 * 32 * 128 + 64 + 128) * 4;     // 84736
    const int NODE_SMEM = (64 * 132 * 2 + 2 * 32 * 128) * 4;                      // 100352
    cudaFuncSetAttribute(pre_kernel,  cudaFuncAttributeMaxDynamicSharedMemorySize, PRE_SMEM);
    cudaFuncSetAttribute(edge_kernel, cudaFuncAttributeMaxDynamicSharedMemorySize, EDGE_SMEM);
    cudaFuncSetAttribute(node_kernel, cudaFuncAttributeMaxDynamicSharedMemorySize, NODE_SMEM);

    pre_kernel<<<(N + 63) / 64, 256, PRE_SMEM>>>(x, ln1g, ln1b, Wg1, Wa1, Wm1, N);
    init_kernel<<<(N * H + 255) / 256, 256>>>(N);
    edge_kernel<<<(E + 63) / 64, 256, EDGE_SMEM>>>(
        esrc, edst, emb, Wm1, bm1, Wm2, bm2, Wa1, ba1, Wa2, ba2,
        Wg1, bg1, Wg2, bg2, E);
    smax_kernel<<<(E + 255) / 256, 256>>>(edst, E);
    exps_kernel<<<(E + 255) / 256, 256>>>(edst, E);
    scatter_kernel<<<((size_t)E * 32 + 255) / 256, 256>>>(edst, out_edges, E);
    node_kernel<<<(N + 63) / 64, 256, NODE_SMEM>>>(
        x, Wself, bself, Wagg, bagg, ln2g, ln2b, Wf1, bf1, Wf2, bf2,
        out_nodes, N);
}